// round 11
// baseline (speedup 1.0000x reference)
#include <cuda_runtime.h>

#define S_ 2048
#define B_ 64
#define D_ 512
#define H_ 8
#define HD_ 64
#define NC_ 64
#define CR_ 32            // rows per chunk = S_/NC_
#define LNEPS 1e-5f

// ---- scratch (static device globals; no runtime allocation) ----
__device__ float g_qproj[B_ * H_ * D_];              // 1 MB
__device__ float g_accb[(size_t)B_ * NC_ * H_ * D_]; // 67 MB
__device__ float g_m[B_ * NC_ * H_];
__device__ float g_l[B_ * NC_ * H_];
__device__ float g_ctx[B_ * D_];
__device__ float g_attn[B_ * D_];

union FU { float4 f4; ulonglong2 u2; };
union FU1 { unsigned long long u; float2 f2; };

__device__ __forceinline__ void fma2(unsigned long long& d,
                                     unsigned long long a,
                                     unsigned long long b) {
    asm("fma.rn.f32x2 %0, %1, %2, %0;" : "+l"(d) : "l"(a), "l"(b));
}

__device__ __forceinline__ float wsum(float v) {
#pragma unroll
    for (int o = 16; o; o >>= 1) v += __shfl_xor_sync(0xffffffffu, v, o);
    return v;
}
__device__ __forceinline__ float wmax(float v) {
#pragma unroll
    for (int o = 16; o; o >>= 1) v = fmaxf(v, __shfl_xor_sync(0xffffffffu, v, o));
    return v;
}

// ============================================================
// K1: block (h, b): q_h = (qin @ Wq_h^T + bq_h)*scale  (64 vals)
//     qproj[b,h,:] = sum_j q_h[j] * Wk[D_+h*64+j, :]
// grid = (H_, B_), block = 128
// ============================================================
__global__ __launch_bounds__(128) void k1(const float* __restrict__ src,
                                          const int* __restrict__ lens,
                                          const float* __restrict__ W,
                                          const float* __restrict__ bias) {
    int h = blockIdx.x, b = blockIdx.y;
    int t = threadIdx.x, w = t >> 5, lane = t & 31;
    __shared__ float4 qin4[D_ / 4];
    __shared__ float qh[HD_];

    int s0 = lens[b] - 1;
    qin4[t] = ((const float4*)(src + ((size_t)s0 * B_ + b) * D_))[t];
    __syncthreads();

#pragma unroll
    for (int i = 0; i < 16; i++) {
        int j = w * 16 + i;
        const float4* wr = (const float4*)(W + (size_t)(h * HD_ + j) * D_);
        float a = 0.f;
#pragma unroll
        for (int kk = 0; kk < 4; kk++) {
            float4 w4 = wr[lane + 32 * kk];
            float4 x4 = qin4[lane + 32 * kk];
            a += w4.x * x4.x + w4.y * x4.y + w4.z * x4.z + w4.w * x4.w;
        }
        a = wsum(a);
        if (lane == 0) qh[j] = (a + bias[h * HD_ + j]) * 0.125f;
    }
    __syncthreads();

    float4 acc = make_float4(0.f, 0.f, 0.f, 0.f);
    const float4* wk = (const float4*)(W + (size_t)(D_ + h * HD_) * D_) + t;
#pragma unroll 8
    for (int j = 0; j < HD_; j++) {
        float qv = qh[j];
        float4 w4 = wk[(size_t)j * (D_ / 4)];
        acc.x += qv * w4.x;
        acc.y += qv * w4.y;
        acc.z += qv * w4.z;
        acc.w += qv * w4.w;
    }
    ((float4*)(g_qproj + ((size_t)b * H_ + h) * D_))[t] = acc;
}

// ============================================================
// K2: flash chunk pass, FFMA2 packed math (R8-proven structure).
// grid = (NC_, B_), block = 256, 2 CTAs/SM.
// smem: qp[4096] | data[16384] | sc_raw[256] | sc2[512]
// ============================================================
__global__ __launch_bounds__(256, 2) void k2(const float* __restrict__ src) {
    extern __shared__ float smem[];
    float* qp = smem;                     // H_*D_
    float* data = qp + H_ * D_;           // CR_*D_
    float* sc_raw = data + CR_ * D_;      // CR_*8
    float* sc2 = sc_raw + CR_ * 8;        // CR_*16 (duplicated pairs)

    int c = blockIdx.x, b = blockIdx.y;
    int t = threadIdx.x, w = t >> 5, lane = t & 31;

    for (int i = t; i < H_ * D_ / 4; i += 256)
        ((float4*)qp)[i] = ((const float4*)(g_qproj + (size_t)b * H_ * D_))[i];
    __syncthreads();

    const float* srcb = src + ((size_t)c * CR_ * B_ + b) * D_;

    // ---------- Phase A: scores (packed f32x2) + stage rows ----------
    {
        int r0 = w * 4;
        unsigned long long p2[4][8];
#pragma unroll
        for (int rr = 0; rr < 4; rr++)
#pragma unroll
            for (int h = 0; h < 8; h++) p2[rr][h] = 0ull;

#pragma unroll
        for (int i = 0; i < 4; i++) {
            int fi = lane + 32 * i;
            FU s[4];
#pragma unroll
            for (int rr = 0; rr < 4; rr++) {
                s[rr].f4 = ((const float4*)(srcb + (size_t)(r0 + rr) * B_ * D_))[fi];
                ((float4*)(data + (size_t)(r0 + rr) * D_))[fi] = s[rr].f4;
            }
#pragma unroll
            for (int h = 0; h < 8; h++) {
                FU q;
                q.f4 = ((const float4*)(qp + h * D_))[fi];
#pragma unroll
                for (int rr = 0; rr < 4; rr++) {
                    fma2(p2[rr][h], s[rr].u2.x, q.u2.x);
                    fma2(p2[rr][h], s[rr].u2.y, q.u2.y);
                }
            }
        }
#pragma unroll
        for (int rr = 0; rr < 4; rr++)
#pragma unroll
            for (int h = 0; h < 8; h++) {
                FU1 pv; pv.u = p2[rr][h];
                float v = wsum(pv.f2.x + pv.f2.y);
                if (lane == 0) sc_raw[(r0 + rr) * 8 + h] = v;
            }
    }
    __syncthreads();

    // ---------- softmax: warp w = head w; write duplicated pairs ----------
    {
        int h = w;
        float v = sc_raw[lane * 8 + h];
        float m = wmax(v);
        float e = __expf(v - m);
        float l = wsum(e);
        sc2[lane * 16 + 2 * h] = e;
        sc2[lane * 16 + 2 * h + 1] = e;
        if (lane == 0) {
            g_m[(b * NC_ + c) * H_ + h] = m;
            g_l[(b * NC_ + c) * H_ + h] = l;
        }
    }
    __syncthreads();

    // ---------- Phase B: packed weighted accumulation, s split in halves ----------
    int half = t >> 7, f = t & 127;
    unsigned long long a2[8][2];
#pragma unroll
    for (int h = 0; h < 8; h++) { a2[h][0] = 0ull; a2[h][1] = 0ull; }

    int sbase = half * (CR_ / 2);
#pragma unroll 4
    for (int si = 0; si < CR_ / 2; si++) {
        int s = sbase + si;
        FU v;
        v.f4 = ((const float4*)data)[s * (D_ / 4) + f];
#pragma unroll
        for (int q = 0; q < 4; q++) {
            FU e;
            e.f4 = *(const float4*)(sc2 + s * 16 + q * 4);
            fma2(a2[2 * q][0], v.u2.x, e.u2.x);
            fma2(a2[2 * q][1], v.u2.y, e.u2.x);
            fma2(a2[2 * q + 1][0], v.u2.x, e.u2.y);
            fma2(a2[2 * q + 1][1], v.u2.y, e.u2.y);
        }
    }
    __syncthreads();

    // half 1 stores partials into reused data smem (padded stride 36 floats)
    if (half) {
#pragma unroll
        for (int h = 0; h < 8; h++) {
            FU o;
            o.u2.x = a2[h][0];
            o.u2.y = a2[h][1];
            ((float4*)(data + f * 36))[h] = o.f4;
        }
    }
    __syncthreads();
    if (!half) {
        float* ab = g_accb + ((size_t)(b * NC_ + c) * H_) * D_;
#pragma unroll
        for (int h = 0; h < 8; h++) {
            FU m_;
            m_.u2.x = a2[h][0];
            m_.u2.y = a2[h][1];
            float4 o = ((const float4*)(data + f * 36))[h];
            o.x += m_.f4.x; o.y += m_.f4.y; o.z += m_.f4.z; o.w += m_.f4.w;
            ((float4*)(ab + h * D_))[f] = o;
        }
    }
}

// ============================================================
// K3ab: per (b,h): combine NC_ chunks with LSE weights, then project
// via Wv. grid = (H_, B_), block = 256
// ============================================================
__global__ __launch_bounds__(256) void k3ab(const float* __restrict__ W,
                                            const float* __restrict__ bias) {
    int h = blockIdx.x, b = blockIdx.y;
    int t = threadIdx.x, w = t >> 5, lane = t & 31;
    __shared__ float wgt[NC_];
    __shared__ float4 cs4[D_ / 4];
    __shared__ float4 part[D_ / 4];

    if (t < 32) {
        float m0 = g_m[(b * NC_ + lane) * H_ + h];
        float m1 = g_m[(b * NC_ + lane + 32) * H_ + h];
        float l0 = g_l[(b * NC_ + lane) * H_ + h];
        float l1 = g_l[(b * NC_ + lane + 32) * H_ + h];
        float m = wmax(fmaxf(m0, m1));
        float w0 = __expf(m0 - m);
        float w1 = __expf(m1 - m);
        float L = wsum(w0 * l0 + w1 * l1);
        wgt[lane] = w0 / L;
        wgt[lane + 32] = w1 / L;
    }
    __syncthreads();

    int half = t >> 7, f = t & 127;
    float4 acc = make_float4(0.f, 0.f, 0.f, 0.f);
    const float4* base = (const float4*)(g_accb + ((size_t)b * NC_ * H_ + h) * D_) + f;
#pragma unroll 4
    for (int cc = half * 32; cc < half * 32 + 32; cc++) {
        float4 v = base[(size_t)cc * H_ * D_ / 4];
        float wv = wgt[cc];
        acc.x += wv * v.x;
        acc.y += wv * v.y;
        acc.z += wv * v.z;
        acc.w += wv * v.w;
    }
    if (half) part[f] = acc;
    __syncthreads();
    if (!half) {
        float4 p = part[f];
        acc.x += p.x; acc.y += p.y; acc.z += p.z; acc.w += p.w;
        cs4[f] = acc;
    }
    __syncthreads();

#pragma unroll
    for (int ii = 0; ii < 8; ii++) {
        int ol = ii * 8 + w;
        const float4* wr = (const float4*)(W + (size_t)(2 * D_ + h * HD_ + ol) * D_);
        float a = 0.f;
#pragma unroll
        for (int kk = 0; kk < 4; kk++) {
            float4 w4 = wr[lane + 32 * kk];
            float4 x4 = cs4[lane + 32 * kk];
            a += w4.x * x4.x + w4.y * x4.y + w4.z * x4.z + w4.w * x4.w;
        }
        a = wsum(a);
        if (lane == 0)
            g_ctx[b * D_ + h * HD_ + ol] = a + bias[2 * D_ + h * HD_ + ol];
    }
}

// ============================================================
// K3c: attn_out[b, i] = g_ctx[b,:] . Wo[i,:] + bo[i]
// grid = (16, B_), block = 256 — 32 outputs per block
// ============================================================
__global__ __launch_bounds__(256) void k3c(const float* __restrict__ Wo,
                                           const float* __restrict__ bo) {
    int gx = blockIdx.x, b = blockIdx.y;
    int t = threadIdx.x, w = t >> 5, lane = t & 31;
    __shared__ float4 cx4[D_ / 4];
    if (t < 128) cx4[t] = ((const float4*)(g_ctx + (size_t)b * D_))[t];
    __syncthreads();

#pragma unroll
    for (int ii = 0; ii < 4; ii++) {
        int i = gx * 32 + ii * 8 + w;
        const float4* wr = (const float4*)(Wo + (size_t)i * D_);
        float a = 0.f;
#pragma unroll
        for (int kk = 0; kk < 4; kk++) {
            float4 w4 = wr[lane + 32 * kk];
            float4 x4 = cx4[lane + 32 * kk];
            a += w4.x * x4.x + w4.y * x4.y + w4.z * x4.z + w4.w * x4.w;
        }
        a = wsum(a);
        if (lane == 0) g_attn[b * D_ + i] = a + bo[i];
    }
}

// ============================================================
// K4: out[s,b,:] = LN(src[s,b,:] + attn_out[b,:])
// warp per row; grid = S_*B_/8, block = 256
// ============================================================
__global__ __launch_bounds__(256) void k4(const float* __restrict__ src,
                                          const float* __restrict__ lnw,
                                          const float* __restrict__ lnb,
                                          float* __restrict__ out) {
    int r = blockIdx.x * 8 + (threadIdx.x >> 5);
    int lane = threadIdx.x & 31;
    int b = r & (B_ - 1);
    const float4* xs = (const float4*)(src + (size_t)r * D_);
    const float4* ao = (const float4*)(g_attn + b * D_);
    float4 x[4];
    float sum = 0.f, sq = 0.f;
#pragma unroll
    for (int i = 0; i < 4; i++) {
        int fi = lane + 32 * i;
        float4 a = __ldcs(xs + fi);
        float4 c = ao[fi];
        a.x += c.x; a.y += c.y; a.z += c.z; a.w += c.w;
        x[i] = a;
        sum += a.x + a.y + a.z + a.w;
        sq += a.x * a.x + a.y * a.y + a.z * a.z + a.w * a.w;
    }
    sum = wsum(sum);
    sq = wsum(sq);
    float mean = sum * (1.f / D_);
    float var = sq * (1.f / D_) - mean * mean;
    float rstd = rsqrtf(var + LNEPS);
    float4* op = (float4*)(out + (size_t)r * D_);
    const float4* w4p = (const float4*)lnw;
    const float4* b4p = (const float4*)lnb;
#pragma unroll
    for (int i = 0; i < 4; i++) {
        int fi = lane + 32 * i;
        float4 wv = w4p[fi];
        float4 bv = b4p[fi];
        float4 a = x[i];
        a.x = (a.x - mean) * rstd * wv.x + bv.x;
        a.y = (a.y - mean) * rstd * wv.y + bv.y;
        a.z = (a.z - mean) * rstd * wv.z + bv.z;
        a.w = (a.w - mean) * rstd * wv.w + bv.w;
        __stcs(op + fi, a);
    }
}

extern "C" void kernel_launch(void* const* d_in, const int* in_sizes, int n_in,
                              void* d_out, int out_size) {
    (void)in_sizes; (void)n_in; (void)out_size;
    const float* src  = (const float*)d_in[0];
    const int*   lens = (const int*)d_in[1];
    const float* W    = (const float*)d_in[2];
    const float* bias = (const float*)d_in[3];
    const float* Wo   = (const float*)d_in[4];
    const float* bo   = (const float*)d_in[5];
    const float* lnw  = (const float*)d_in[6];
    const float* lnb  = (const float*)d_in[7];
    float* out = (float*)d_out;

    const int k2_smem = (H_ * D_ + CR_ * D_ + CR_ * 8 + CR_ * 16) * sizeof(float);
    static bool attr_set = false;
    if (!attr_set) {
        cudaFuncSetAttribute(k2, cudaFuncAttributeMaxDynamicSharedMemorySize, k2_smem);
        attr_set = true;
    }

    k1<<<dim3(H_, B_), 128>>>(src, lens, W, bias);
    k2<<<dim3(NC_, B_), 256, k2_smem>>>(src);
    k3ab<<<dim3(H_, B_), 256>>>(W, bias);
    k3c<<<dim3(16, B_), 256>>>(Wo, bo);
    k4<<<(S_ * B_) / 8, 256>>>(src, lnw, lnb, out);
}

// round 12
// speedup vs baseline: 1.3193x; 1.3193x over previous
#include <cuda_runtime.h>

#define S_ 2048
#define B_ 64
#define D_ 512
#define H_ 8
#define HD_ 64
#define NC_ 64
#define CR_ 32            // rows per chunk = S_/NC_
#define LNEPS 1e-5f

// ---- scratch (static device globals; no runtime allocation) ----
__device__ float g_qproj[B_ * H_ * D_];              // 1 MB
__device__ float g_accb[(size_t)B_ * NC_ * H_ * D_]; // 67 MB
__device__ float g_m[B_ * NC_ * H_];
__device__ float g_l[B_ * NC_ * H_];
__device__ float g_ctx[B_ * D_];
__device__ float g_attn[B_ * D_];

union FU { float4 f4; ulonglong2 u2; };
union FU1 { unsigned long long u; float2 f2; };

__device__ __forceinline__ void fma2(unsigned long long& d,
                                     unsigned long long a,
                                     unsigned long long b) {
    asm("fma.rn.f32x2 %0, %1, %2, %0;" : "+l"(d) : "l"(a), "l"(b));
}

__device__ __forceinline__ float wsum(float v) {
#pragma unroll
    for (int o = 16; o; o >>= 1) v += __shfl_xor_sync(0xffffffffu, v, o);
    return v;
}
__device__ __forceinline__ float wmax(float v) {
#pragma unroll
    for (int o = 16; o; o >>= 1) v = fmaxf(v, __shfl_xor_sync(0xffffffffu, v, o));
    return v;
}

// ============================================================
// K1: block (h, b): q_h = (qin @ Wq_h^T + bq_h)*scale  (64 vals)
//     qproj[b,h,:] = sum_j q_h[j] * Wk[D_+h*64+j, :]
// grid = (H_, B_), block = 128
// ============================================================
__global__ __launch_bounds__(128) void k1(const float* __restrict__ src,
                                          const int* __restrict__ lens,
                                          const float* __restrict__ W,
                                          const float* __restrict__ bias) {
    int h = blockIdx.x, b = blockIdx.y;
    int t = threadIdx.x, w = t >> 5, lane = t & 31;
    __shared__ float4 qin4[D_ / 4];
    __shared__ float qh[HD_];

    int s0 = lens[b] - 1;
    qin4[t] = ((const float4*)(src + ((size_t)s0 * B_ + b) * D_))[t];
    __syncthreads();

#pragma unroll
    for (int i = 0; i < 16; i++) {
        int j = w * 16 + i;
        const float4* wr = (const float4*)(W + (size_t)(h * HD_ + j) * D_);
        float a = 0.f;
#pragma unroll
        for (int kk = 0; kk < 4; kk++) {
            float4 w4 = wr[lane + 32 * kk];
            float4 x4 = qin4[lane + 32 * kk];
            a += w4.x * x4.x + w4.y * x4.y + w4.z * x4.z + w4.w * x4.w;
        }
        a = wsum(a);
        if (lane == 0) qh[j] = (a + bias[h * HD_ + j]) * 0.125f;
    }
    __syncthreads();

    float4 acc = make_float4(0.f, 0.f, 0.f, 0.f);
    const float4* wk = (const float4*)(W + (size_t)(D_ + h * HD_) * D_) + t;
#pragma unroll 8
    for (int j = 0; j < HD_; j++) {
        float qv = qh[j];
        float4 w4 = wk[(size_t)j * (D_ / 4)];
        acc.x += qv * w4.x;
        acc.y += qv * w4.y;
        acc.z += qv * w4.z;
        acc.w += qv * w4.w;
    }
    ((float4*)(g_qproj + ((size_t)b * H_ + h) * D_))[t] = acc;
}

// ============================================================
// K2: flash chunk pass, FFMA2 packed math (R8-proven structure).
// grid = (NC_, B_), block = 256, 2 CTAs/SM.
// smem: qp[4096] | data[16384] | sc_raw[256] | sc2[512]
// ============================================================
__global__ __launch_bounds__(256, 2) void k2(const float* __restrict__ src) {
    extern __shared__ float smem[];
    float* qp = smem;                     // H_*D_
    float* data = qp + H_ * D_;           // CR_*D_
    float* sc_raw = data + CR_ * D_;      // CR_*8
    float* sc2 = sc_raw + CR_ * 8;        // CR_*16 (duplicated pairs)

    int c = blockIdx.x, b = blockIdx.y;
    int t = threadIdx.x, w = t >> 5, lane = t & 31;

    for (int i = t; i < H_ * D_ / 4; i += 256)
        ((float4*)qp)[i] = ((const float4*)(g_qproj + (size_t)b * H_ * D_))[i];
    __syncthreads();

    const float* srcb = src + ((size_t)c * CR_ * B_ + b) * D_;

    // ---------- Phase A: scores (packed f32x2) + stage rows ----------
    {
        int r0 = w * 4;
        unsigned long long p2[4][8];
#pragma unroll
        for (int rr = 0; rr < 4; rr++)
#pragma unroll
            for (int h = 0; h < 8; h++) p2[rr][h] = 0ull;

#pragma unroll
        for (int i = 0; i < 4; i++) {
            int fi = lane + 32 * i;
            FU s[4];
#pragma unroll
            for (int rr = 0; rr < 4; rr++) {
                s[rr].f4 = ((const float4*)(srcb + (size_t)(r0 + rr) * B_ * D_))[fi];
                ((float4*)(data + (size_t)(r0 + rr) * D_))[fi] = s[rr].f4;
            }
#pragma unroll
            for (int h = 0; h < 8; h++) {
                FU q;
                q.f4 = ((const float4*)(qp + h * D_))[fi];
#pragma unroll
                for (int rr = 0; rr < 4; rr++) {
                    fma2(p2[rr][h], s[rr].u2.x, q.u2.x);
                    fma2(p2[rr][h], s[rr].u2.y, q.u2.y);
                }
            }
        }
#pragma unroll
        for (int rr = 0; rr < 4; rr++)
#pragma unroll
            for (int h = 0; h < 8; h++) {
                FU1 pv; pv.u = p2[rr][h];
                float v = wsum(pv.f2.x + pv.f2.y);
                if (lane == 0) sc_raw[(r0 + rr) * 8 + h] = v;
            }
    }
    __syncthreads();

    // ---------- softmax: warp w = head w; write duplicated pairs ----------
    {
        int h = w;
        float v = sc_raw[lane * 8 + h];
        float m = wmax(v);
        float e = __expf(v - m);
        float l = wsum(e);
        sc2[lane * 16 + 2 * h] = e;
        sc2[lane * 16 + 2 * h + 1] = e;
        if (lane == 0) {
            g_m[(b * NC_ + c) * H_ + h] = m;
            g_l[(b * NC_ + c) * H_ + h] = l;
        }
    }
    __syncthreads();

    // ---------- Phase B: packed weighted accumulation, s split in halves ----------
    int half = t >> 7, f = t & 127;
    unsigned long long a2[8][2];
#pragma unroll
    for (int h = 0; h < 8; h++) { a2[h][0] = 0ull; a2[h][1] = 0ull; }

    int sbase = half * (CR_ / 2);
#pragma unroll 2
    for (int si = 0; si < CR_ / 2; si++) {
        int s = sbase + si;
        FU v;
        v.f4 = ((const float4*)data)[s * (D_ / 4) + f];
#pragma unroll
        for (int q = 0; q < 4; q++) {
            FU e;
            e.f4 = *(const float4*)(sc2 + s * 16 + q * 4);
            fma2(a2[2 * q][0], v.u2.x, e.u2.x);
            fma2(a2[2 * q][1], v.u2.y, e.u2.x);
            fma2(a2[2 * q + 1][0], v.u2.x, e.u2.y);
            fma2(a2[2 * q + 1][1], v.u2.y, e.u2.y);
        }
    }
    __syncthreads();

    // half 1 stores partials into reused data smem (padded stride 36 floats)
    if (half) {
#pragma unroll
        for (int h = 0; h < 8; h++) {
            FU o;
            o.u2.x = a2[h][0];
            o.u2.y = a2[h][1];
            ((float4*)(data + f * 36))[h] = o.f4;
        }
    }
    __syncthreads();
    if (!half) {
        float* ab = g_accb + ((size_t)(b * NC_ + c) * H_) * D_;
#pragma unroll
        for (int h = 0; h < 8; h++) {
            FU m_;
            m_.u2.x = a2[h][0];
            m_.u2.y = a2[h][1];
            float4 o = ((const float4*)(data + f * 36))[h];
            o.x += m_.f4.x; o.y += m_.f4.y; o.z += m_.f4.z; o.w += m_.f4.w;
            ((float4*)(ab + h * D_))[f] = o;
        }
    }
}

// ============================================================
// K3ab: per (b,h): combine NC_ chunks with LSE weights, then project
// via Wv. grid = (H_, B_), block = 256
// ============================================================
__global__ __launch_bounds__(256) void k3ab(const float* __restrict__ W,
                                            const float* __restrict__ bias) {
    int h = blockIdx.x, b = blockIdx.y;
    int t = threadIdx.x, w = t >> 5, lane = t & 31;
    __shared__ float wgt[NC_];
    __shared__ float4 cs4[D_ / 4];
    __shared__ float4 part[D_ / 4];

    if (t < 32) {
        float m0 = g_m[(b * NC_ + lane) * H_ + h];
        float m1 = g_m[(b * NC_ + lane + 32) * H_ + h];
        float l0 = g_l[(b * NC_ + lane) * H_ + h];
        float l1 = g_l[(b * NC_ + lane + 32) * H_ + h];
        float m = wmax(fmaxf(m0, m1));
        float w0 = __expf(m0 - m);
        float w1 = __expf(m1 - m);
        float L = wsum(w0 * l0 + w1 * l1);
        wgt[lane] = w0 / L;
        wgt[lane + 32] = w1 / L;
    }
    __syncthreads();

    int half = t >> 7, f = t & 127;
    float4 acc = make_float4(0.f, 0.f, 0.f, 0.f);
    const float4* base = (const float4*)(g_accb + ((size_t)b * NC_ * H_ + h) * D_) + f;
#pragma unroll 4
    for (int cc = half * 32; cc < half * 32 + 32; cc++) {
        float4 v = base[(size_t)cc * H_ * D_ / 4];
        float wv = wgt[cc];
        acc.x += wv * v.x;
        acc.y += wv * v.y;
        acc.z += wv * v.z;
        acc.w += wv * v.w;
    }
    if (half) part[f] = acc;
    __syncthreads();
    if (!half) {
        float4 p = part[f];
        acc.x += p.x; acc.y += p.y; acc.z += p.z; acc.w += p.w;
        cs4[f] = acc;
    }
    __syncthreads();

#pragma unroll
    for (int ii = 0; ii < 8; ii++) {
        int ol = ii * 8 + w;
        const float4* wr = (const float4*)(W + (size_t)(2 * D_ + h * HD_ + ol) * D_);
        float a = 0.f;
#pragma unroll
        for (int kk = 0; kk < 4; kk++) {
            float4 w4 = wr[lane + 32 * kk];
            float4 x4 = cs4[lane + 32 * kk];
            a += w4.x * x4.x + w4.y * x4.y + w4.z * x4.z + w4.w * x4.w;
        }
        a = wsum(a);
        if (lane == 0)
            g_ctx[b * D_ + h * HD_ + ol] = a + bias[2 * D_ + h * HD_ + ol];
    }
}

// ============================================================
// K3c: attn_out[b, i] = g_ctx[b,:] . Wo[i,:] + bo[i]
// grid = (8, B_), block = 256
// ============================================================
__global__ __launch_bounds__(256) void k3c(const float* __restrict__ Wo,
                                           const float* __restrict__ bo) {
    int gx = blockIdx.x, b = blockIdx.y;
    int t = threadIdx.x, w = t >> 5, lane = t & 31;
    __shared__ float4 cx4[D_ / 4];
    if (t < 128) cx4[t] = ((const float4*)(g_ctx + (size_t)b * D_))[t];
    __syncthreads();

#pragma unroll
    for (int ii = 0; ii < 8; ii++) {
        int i = gx * 64 + ii * 8 + w;
        const float4* wr = (const float4*)(Wo + (size_t)i * D_);
        float a = 0.f;
#pragma unroll
        for (int kk = 0; kk < 4; kk++) {
            float4 w4 = wr[lane + 32 * kk];
            float4 x4 = cx4[lane + 32 * kk];
            a += w4.x * x4.x + w4.y * x4.y + w4.z * x4.z + w4.w * x4.w;
        }
        a = wsum(a);
        if (lane == 0) g_attn[b * D_ + i] = a + bo[i];
    }
}

// ============================================================
// K4: out[s,b,:] = LN(src[s,b,:] + attn_out[b,:])
// warp per row; grid = S_*B_/8, block = 256
// ============================================================
__global__ __launch_bounds__(256) void k4(const float* __restrict__ src,
                                          const float* __restrict__ lnw,
                                          const float* __restrict__ lnb,
                                          float* __restrict__ out) {
    int r = blockIdx.x * 8 + (threadIdx.x >> 5);
    int lane = threadIdx.x & 31;
    int b = r & (B_ - 1);
    const float4* xs = (const float4*)(src + (size_t)r * D_);
    const float4* ao = (const float4*)(g_attn + b * D_);
    float4 x[4];
    float sum = 0.f, sq = 0.f;
#pragma unroll
    for (int i = 0; i < 4; i++) {
        int fi = lane + 32 * i;
        float4 a = __ldcs(xs + fi);
        float4 c = ao[fi];
        a.x += c.x; a.y += c.y; a.z += c.z; a.w += c.w;
        x[i] = a;
        sum += a.x + a.y + a.z + a.w;
        sq += a.x * a.x + a.y * a.y + a.z * a.z + a.w * a.w;
    }
    sum = wsum(sum);
    sq = wsum(sq);
    float mean = sum * (1.f / D_);
    float var = sq * (1.f / D_) - mean * mean;
    float rstd = rsqrtf(var + LNEPS);
    float4* op = (float4*)(out + (size_t)r * D_);
    const float4* w4p = (const float4*)lnw;
    const float4* b4p = (const float4*)lnb;
#pragma unroll
    for (int i = 0; i < 4; i++) {
        int fi = lane + 32 * i;
        float4 wv = w4p[fi];
        float4 bv = b4p[fi];
        float4 a = x[i];
        a.x = (a.x - mean) * rstd * wv.x + bv.x;
        a.y = (a.y - mean) * rstd * wv.y + bv.y;
        a.z = (a.z - mean) * rstd * wv.z + bv.z;
        a.w = (a.w - mean) * rstd * wv.w + bv.w;
        __stcs(op + fi, a);
    }
}

extern "C" void kernel_launch(void* const* d_in, const int* in_sizes, int n_in,
                              void* d_out, int out_size) {
    (void)in_sizes; (void)n_in; (void)out_size;
    const float* src  = (const float*)d_in[0];
    const int*   lens = (const int*)d_in[1];
    const float* W    = (const float*)d_in[2];
    const float* bias = (const float*)d_in[3];
    const float* Wo   = (const float*)d_in[4];
    const float* bo   = (const float*)d_in[5];
    const float* lnw  = (const float*)d_in[6];
    const float* lnb  = (const float*)d_in[7];
    float* out = (float*)d_out;

    const int k2_smem = (H_ * D_ + CR_ * D_ + CR_ * 8 + CR_ * 16) * sizeof(float);
    static bool attr_set = false;
    if (!attr_set) {
        cudaFuncSetAttribute(k2, cudaFuncAttributeMaxDynamicSharedMemorySize, k2_smem);
        attr_set = true;
    }

    k1<<<dim3(H_, B_), 128>>>(src, lens, W, bias);
    k2<<<dim3(NC_, B_), 256, k2_smem>>>(src);
    k3ab<<<dim3(H_, B_), 256>>>(W, bias);
    k3c<<<dim3(8, B_), 256>>>(Wo, bo);
    k4<<<(S_ * B_) / 8, 256>>>(src, lnw, lnb, out);
}

// round 13
// speedup vs baseline: 1.3312x; 1.0090x over previous
#include <cuda_runtime.h>

#define S_ 2048
#define B_ 64
#define D_ 512
#define H_ 8
#define HD_ 64
#define NC_ 64
#define CR_ 32            // rows per chunk = S_/NC_
#define LNEPS 1e-5f

// ---- scratch (static device globals; no runtime allocation) ----
__device__ float g_qproj[B_ * H_ * D_];              // 1 MB
__device__ float g_accb[(size_t)B_ * NC_ * H_ * D_]; // 67 MB
__device__ float g_m[B_ * NC_ * H_];
__device__ float g_l[B_ * NC_ * H_];
__device__ float g_ctx[B_ * D_];
__device__ float g_attn[B_ * D_];

union FU { float4 f4; ulonglong2 u2; };
union FU1 { unsigned long long u; float2 f2; };

__device__ __forceinline__ void fma2(unsigned long long& d,
                                     unsigned long long a,
                                     unsigned long long b) {
    asm("fma.rn.f32x2 %0, %1, %2, %0;" : "+l"(d) : "l"(a), "l"(b));
}

__device__ __forceinline__ float wsum(float v) {
#pragma unroll
    for (int o = 16; o; o >>= 1) v += __shfl_xor_sync(0xffffffffu, v, o);
    return v;
}
__device__ __forceinline__ float wmax(float v) {
#pragma unroll
    for (int o = 16; o; o >>= 1) v = fmaxf(v, __shfl_xor_sync(0xffffffffu, v, o));
    return v;
}

// ============================================================
// K1: block (h, b): q_h = (qin @ Wq_h^T + bq_h)*scale  (64 vals)
//     qproj[b,h,:] = sum_j q_h[j] * Wk[D_+h*64+j, :]
// grid = (H_, B_), block = 128
// ============================================================
__global__ __launch_bounds__(128) void k1(const float* __restrict__ src,
                                          const int* __restrict__ lens,
                                          const float* __restrict__ W,
                                          const float* __restrict__ bias) {
    int h = blockIdx.x, b = blockIdx.y;
    int t = threadIdx.x, w = t >> 5, lane = t & 31;
    __shared__ float4 qin4[D_ / 4];
    __shared__ float qh[HD_];

    int s0 = lens[b] - 1;
    qin4[t] = ((const float4*)(src + ((size_t)s0 * B_ + b) * D_))[t];
    __syncthreads();

#pragma unroll
    for (int i = 0; i < 16; i++) {
        int j = w * 16 + i;
        const float4* wr = (const float4*)(W + (size_t)(h * HD_ + j) * D_);
        float a = 0.f;
#pragma unroll
        for (int kk = 0; kk < 4; kk++) {
            float4 w4 = wr[lane + 32 * kk];
            float4 x4 = qin4[lane + 32 * kk];
            a += w4.x * x4.x + w4.y * x4.y + w4.z * x4.z + w4.w * x4.w;
        }
        a = wsum(a);
        if (lane == 0) qh[j] = (a + bias[h * HD_ + j]) * 0.125f;
    }
    __syncthreads();

    float4 acc = make_float4(0.f, 0.f, 0.f, 0.f);
    const float4* wk = (const float4*)(W + (size_t)(D_ + h * HD_) * D_) + t;
#pragma unroll 8
    for (int j = 0; j < HD_; j++) {
        float qv = qh[j];
        float4 w4 = wk[(size_t)j * (D_ / 4)];
        acc.x += qv * w4.x;
        acc.y += qv * w4.y;
        acc.z += qv * w4.z;
        acc.w += qv * w4.w;
    }
    ((float4*)(g_qproj + ((size_t)b * H_ + h) * D_))[t] = acc;
}

// ============================================================
// K2: flash chunk pass, FFMA2 packed math (R8-proven structure; FROZEN).
// grid = (NC_, B_), block = 256, 2 CTAs/SM.
// smem: qp[4096] | data[16384] | sc_raw[256] | sc2[512]
// ============================================================
__global__ __launch_bounds__(256, 2) void k2(const float* __restrict__ src) {
    extern __shared__ float smem[];
    float* qp = smem;                     // H_*D_
    float* data = qp + H_ * D_;           // CR_*D_
    float* sc_raw = data + CR_ * D_;      // CR_*8
    float* sc2 = sc_raw + CR_ * 8;        // CR_*16 (duplicated pairs)

    int c = blockIdx.x, b = blockIdx.y;
    int t = threadIdx.x, w = t >> 5, lane = t & 31;

    for (int i = t; i < H_ * D_ / 4; i += 256)
        ((float4*)qp)[i] = ((const float4*)(g_qproj + (size_t)b * H_ * D_))[i];
    __syncthreads();

    const float* srcb = src + ((size_t)c * CR_ * B_ + b) * D_;

    // ---------- Phase A: scores (packed f32x2) + stage rows ----------
    {
        int r0 = w * 4;
        unsigned long long p2[4][8];
#pragma unroll
        for (int rr = 0; rr < 4; rr++)
#pragma unroll
            for (int h = 0; h < 8; h++) p2[rr][h] = 0ull;

#pragma unroll
        for (int i = 0; i < 4; i++) {
            int fi = lane + 32 * i;
            FU s[4];
#pragma unroll
            for (int rr = 0; rr < 4; rr++) {
                s[rr].f4 = ((const float4*)(srcb + (size_t)(r0 + rr) * B_ * D_))[fi];
                ((float4*)(data + (size_t)(r0 + rr) * D_))[fi] = s[rr].f4;
            }
#pragma unroll
            for (int h = 0; h < 8; h++) {
                FU q;
                q.f4 = ((const float4*)(qp + h * D_))[fi];
#pragma unroll
                for (int rr = 0; rr < 4; rr++) {
                    fma2(p2[rr][h], s[rr].u2.x, q.u2.x);
                    fma2(p2[rr][h], s[rr].u2.y, q.u2.y);
                }
            }
        }
#pragma unroll
        for (int rr = 0; rr < 4; rr++)
#pragma unroll
            for (int h = 0; h < 8; h++) {
                FU1 pv; pv.u = p2[rr][h];
                float v = wsum(pv.f2.x + pv.f2.y);
                if (lane == 0) sc_raw[(r0 + rr) * 8 + h] = v;
            }
    }
    __syncthreads();

    // ---------- softmax: warp w = head w; write duplicated pairs ----------
    {
        int h = w;
        float v = sc_raw[lane * 8 + h];
        float m = wmax(v);
        float e = __expf(v - m);
        float l = wsum(e);
        sc2[lane * 16 + 2 * h] = e;
        sc2[lane * 16 + 2 * h + 1] = e;
        if (lane == 0) {
            g_m[(b * NC_ + c) * H_ + h] = m;
            g_l[(b * NC_ + c) * H_ + h] = l;
        }
    }
    __syncthreads();

    // ---------- Phase B: packed weighted accumulation, s split in halves ----------
    int half = t >> 7, f = t & 127;
    unsigned long long a2[8][2];
#pragma unroll
    for (int h = 0; h < 8; h++) { a2[h][0] = 0ull; a2[h][1] = 0ull; }

    int sbase = half * (CR_ / 2);
#pragma unroll 2
    for (int si = 0; si < CR_ / 2; si++) {
        int s = sbase + si;
        FU v;
        v.f4 = ((const float4*)data)[s * (D_ / 4) + f];
#pragma unroll
        for (int q = 0; q < 4; q++) {
            FU e;
            e.f4 = *(const float4*)(sc2 + s * 16 + q * 4);
            fma2(a2[2 * q][0], v.u2.x, e.u2.x);
            fma2(a2[2 * q][1], v.u2.y, e.u2.x);
            fma2(a2[2 * q + 1][0], v.u2.x, e.u2.y);
            fma2(a2[2 * q + 1][1], v.u2.y, e.u2.y);
        }
    }
    __syncthreads();

    // half 1 stores partials into reused data smem (padded stride 36 floats)
    if (half) {
#pragma unroll
        for (int h = 0; h < 8; h++) {
            FU o;
            o.u2.x = a2[h][0];
            o.u2.y = a2[h][1];
            ((float4*)(data + f * 36))[h] = o.f4;
        }
    }
    __syncthreads();
    if (!half) {
        float* ab = g_accb + ((size_t)(b * NC_ + c) * H_) * D_;
#pragma unroll
        for (int h = 0; h < 8; h++) {
            FU m_;
            m_.u2.x = a2[h][0];
            m_.u2.y = a2[h][1];
            float4 o = ((const float4*)(data + f * 36))[h];
            o.x += m_.f4.x; o.y += m_.f4.y; o.z += m_.f4.z; o.w += m_.f4.w;
            ((float4*)(ab + h * D_))[f] = o;
        }
    }
}

// ============================================================
// K3ab: per (b,h): combine NC_ chunks with LSE weights, then project
// via Wv. grid = (H_, B_), block = 256
// combine: unroll 8 + __ldcs (accb dead after); proj: 2-way ILP
// ============================================================
__global__ __launch_bounds__(256) void k3ab(const float* __restrict__ W,
                                            const float* __restrict__ bias) {
    int h = blockIdx.x, b = blockIdx.y;
    int t = threadIdx.x, w = t >> 5, lane = t & 31;
    __shared__ float wgt[NC_];
    __shared__ float4 cs4[D_ / 4];
    __shared__ float4 part[D_ / 4];

    if (t < 32) {
        float m0 = g_m[(b * NC_ + lane) * H_ + h];
        float m1 = g_m[(b * NC_ + lane + 32) * H_ + h];
        float l0 = g_l[(b * NC_ + lane) * H_ + h];
        float l1 = g_l[(b * NC_ + lane + 32) * H_ + h];
        float m = wmax(fmaxf(m0, m1));
        float w0 = __expf(m0 - m);
        float w1 = __expf(m1 - m);
        float L = wsum(w0 * l0 + w1 * l1);
        wgt[lane] = w0 / L;
        wgt[lane + 32] = w1 / L;
    }
    __syncthreads();

    int half = t >> 7, f = t & 127;
    float4 acc = make_float4(0.f, 0.f, 0.f, 0.f);
    const float4* base = (const float4*)(g_accb + ((size_t)b * NC_ * H_ + h) * D_) + f;
#pragma unroll 8
    for (int cc = half * 32; cc < half * 32 + 32; cc++) {
        float4 v = __ldcs(base + (size_t)cc * H_ * D_ / 4);
        float wv = wgt[cc];
        acc.x += wv * v.x;
        acc.y += wv * v.y;
        acc.z += wv * v.z;
        acc.w += wv * v.w;
    }
    if (half) part[f] = acc;
    __syncthreads();
    if (!half) {
        float4 p = part[f];
        acc.x += p.x; acc.y += p.y; acc.z += p.z; acc.w += p.w;
        cs4[f] = acc;
    }
    __syncthreads();

    // Wv projection: 2 outputs in flight per warp iteration
#pragma unroll
    for (int ii = 0; ii < 4; ii++) {
        int ol0 = ii * 16 + w;
        int ol1 = ol0 + 8;
        const float4* wr0 = (const float4*)(W + (size_t)(2 * D_ + h * HD_ + ol0) * D_);
        const float4* wr1 = (const float4*)(W + (size_t)(2 * D_ + h * HD_ + ol1) * D_);
        float a0 = 0.f, a1 = 0.f;
#pragma unroll
        for (int kk = 0; kk < 4; kk++) {
            float4 x4 = cs4[lane + 32 * kk];
            float4 w40 = wr0[lane + 32 * kk];
            float4 w41 = wr1[lane + 32 * kk];
            a0 += w40.x * x4.x + w40.y * x4.y + w40.z * x4.z + w40.w * x4.w;
            a1 += w41.x * x4.x + w41.y * x4.y + w41.z * x4.z + w41.w * x4.w;
        }
        a0 = wsum(a0);
        a1 = wsum(a1);
        if (lane == 0) {
            g_ctx[b * D_ + h * HD_ + ol0] = a0 + bias[2 * D_ + h * HD_ + ol0];
            g_ctx[b * D_ + h * HD_ + ol1] = a1 + bias[2 * D_ + h * HD_ + ol1];
        }
    }
}

// ============================================================
// K3c: attn_out[b, i] = g_ctx[b,:] . Wo[i,:] + bo[i]
// grid = (8, B_), block = 256 — 2 outputs in flight per warp iteration
// ============================================================
__global__ __launch_bounds__(256) void k3c(const float* __restrict__ Wo,
                                           const float* __restrict__ bo) {
    int gx = blockIdx.x, b = blockIdx.y;
    int t = threadIdx.x, w = t >> 5, lane = t & 31;
    __shared__ float4 cx4[D_ / 4];
    if (t < 128) cx4[t] = ((const float4*)(g_ctx + (size_t)b * D_))[t];
    __syncthreads();

#pragma unroll
    for (int ii = 0; ii < 4; ii++) {
        int i0 = gx * 64 + ii * 16 + w;
        int i1 = i0 + 8;
        const float4* wr0 = (const float4*)(Wo + (size_t)i0 * D_);
        const float4* wr1 = (const float4*)(Wo + (size_t)i1 * D_);
        float a0 = 0.f, a1 = 0.f;
#pragma unroll
        for (int kk = 0; kk < 4; kk++) {
            float4 x4 = cx4[lane + 32 * kk];
            float4 w40 = wr0[lane + 32 * kk];
            float4 w41 = wr1[lane + 32 * kk];
            a0 += w40.x * x4.x + w40.y * x4.y + w40.z * x4.z + w40.w * x4.w;
            a1 += w41.x * x4.x + w41.y * x4.y + w41.z * x4.z + w41.w * x4.w;
        }
        a0 = wsum(a0);
        a1 = wsum(a1);
        if (lane == 0) {
            g_attn[b * D_ + i0] = a0 + bo[i0];
            g_attn[b * D_ + i1] = a1 + bo[i1];
        }
    }
}

// ============================================================
// K4: out[s,b,:] = LN(src[s,b,:] + attn_out[b,:])
// warp per row; grid = S_*B_/8, block = 256 (FROZEN — at DRAM roofline)
// ============================================================
__global__ __launch_bounds__(256) void k4(const float* __restrict__ src,
                                          const float* __restrict__ lnw,
                                          const float* __restrict__ lnb,
                                          float* __restrict__ out) {
    int r = blockIdx.x * 8 + (threadIdx.x >> 5);
    int lane = threadIdx.x & 31;
    int b = r & (B_ - 1);
    const float4* xs = (const float4*)(src + (size_t)r * D_);
    const float4* ao = (const float4*)(g_attn + b * D_);
    float4 x[4];
    float sum = 0.f, sq = 0.f;
#pragma unroll
    for (int i = 0; i < 4; i++) {
        int fi = lane + 32 * i;
        float4 a = __ldcs(xs + fi);
        float4 c = ao[fi];
        a.x += c.x; a.y += c.y; a.z += c.z; a.w += c.w;
        x[i] = a;
        sum += a.x + a.y + a.z + a.w;
        sq += a.x * a.x + a.y * a.y + a.z * a.z + a.w * a.w;
    }
    sum = wsum(sum);
    sq = wsum(sq);
    float mean = sum * (1.f / D_);
    float var = sq * (1.f / D_) - mean * mean;
    float rstd = rsqrtf(var + LNEPS);
    float4* op = (float4*)(out + (size_t)r * D_);
    const float4* w4p = (const float4*)lnw;
    const float4* b4p = (const float4*)lnb;
#pragma unroll
    for (int i = 0; i < 4; i++) {
        int fi = lane + 32 * i;
        float4 wv = w4p[fi];
        float4 bv = b4p[fi];
        float4 a = x[i];
        a.x = (a.x - mean) * rstd * wv.x + bv.x;
        a.y = (a.y - mean) * rstd * wv.y + bv.y;
        a.z = (a.z - mean) * rstd * wv.z + bv.z;
        a.w = (a.w - mean) * rstd * wv.w + bv.w;
        __stcs(op + fi, a);
    }
}

extern "C" void kernel_launch(void* const* d_in, const int* in_sizes, int n_in,
                              void* d_out, int out_size) {
    (void)in_sizes; (void)n_in; (void)out_size;
    const float* src  = (const float*)d_in[0];
    const int*   lens = (const int*)d_in[1];
    const float* W    = (const float*)d_in[2];
    const float* bias = (const float*)d_in[3];
    const float* Wo   = (const float*)d_in[4];
    const float* bo   = (const float*)d_in[5];
    const float* lnw  = (const float*)d_in[6];
    const float* lnb  = (const float*)d_in[7];
    float* out = (float*)d_out;

    const int k2_smem = (H_ * D_ + CR_ * D_ + CR_ * 8 + CR_ * 16) * sizeof(float);
    static bool attr_set = false;
    if (!attr_set) {
        cudaFuncSetAttribute(k2, cudaFuncAttributeMaxDynamicSharedMemorySize, k2_smem);
        attr_set = true;
    }

    k1<<<dim3(H_, B_), 128>>>(src, lens, W, bias);
    k2<<<dim3(NC_, B_), 256, k2_smem>>>(src);
    k3ab<<<dim3(H_, B_), 256>>>(W, bias);
    k3c<<<dim3(8, B_), 256>>>(Wo, bo);
    k4<<<(S_ * B_) / 8, 256>>>(src, lnw, lnb, out);
}

// round 15
// speedup vs baseline: 1.3848x; 1.0402x over previous
#include <cuda_runtime.h>
#include <cuda_fp16.h>

#define S_ 2048
#define B_ 64
#define D_ 512
#define H_ 8
#define HD_ 64
#define NC_ 64
#define CR_ 32            // rows per chunk = S_/NC_
#define LNEPS 1e-5f

// ---- scratch (static device globals; no runtime allocation) ----
__device__ float g_qproj[B_ * H_ * D_];               // 1 MB
__device__ __half g_accb[(size_t)B_ * NC_ * H_ * D_]; // 33.5 MB (fp16 partials)
__device__ float g_m[B_ * NC_ * H_];
__device__ float g_l[B_ * NC_ * H_];
__device__ float g_ctx[B_ * D_];
__device__ float g_attn[B_ * D_];

union FU { float4 f4; ulonglong2 u2; };
union FU1 { unsigned long long u; float2 f2; };
union HU { uint2 u2; __half2 h2[2]; };

__device__ __forceinline__ void fma2(unsigned long long& d,
                                     unsigned long long a,
                                     unsigned long long b) {
    asm("fma.rn.f32x2 %0, %1, %2, %0;" : "+l"(d) : "l"(a), "l"(b));
}

__device__ __forceinline__ float wsum(float v) {
#pragma unroll
    for (int o = 16; o; o >>= 1) v += __shfl_xor_sync(0xffffffffu, v, o);
    return v;
}
__device__ __forceinline__ float wmax(float v) {
#pragma unroll
    for (int o = 16; o; o >>= 1) v = fmaxf(v, __shfl_xor_sync(0xffffffffu, v, o));
    return v;
}

// ============================================================
// K1: block (h, b): q_h = (qin @ Wq_h^T + bq_h)*scale  (64 vals)
//     qproj[b,h,:] = sum_j q_h[j] * Wk[D_+h*64+j, :]
// grid = (H_, B_), block = 128
// ============================================================
__global__ __launch_bounds__(128) void k1(const float* __restrict__ src,
                                          const int* __restrict__ lens,
                                          const float* __restrict__ W,
                                          const float* __restrict__ bias) {
    int h = blockIdx.x, b = blockIdx.y;
    int t = threadIdx.x, w = t >> 5, lane = t & 31;
    __shared__ float4 qin4[D_ / 4];
    __shared__ float qh[HD_];

    int s0 = lens[b] - 1;
    qin4[t] = ((const float4*)(src + ((size_t)s0 * B_ + b) * D_))[t];
    __syncthreads();

#pragma unroll
    for (int i = 0; i < 16; i++) {
        int j = w * 16 + i;
        const float4* wr = (const float4*)(W + (size_t)(h * HD_ + j) * D_);
        float a = 0.f;
#pragma unroll
        for (int kk = 0; kk < 4; kk++) {
            float4 w4 = wr[lane + 32 * kk];
            float4 x4 = qin4[lane + 32 * kk];
            a += w4.x * x4.x + w4.y * x4.y + w4.z * x4.z + w4.w * x4.w;
        }
        a = wsum(a);
        if (lane == 0) qh[j] = (a + bias[h * HD_ + j]) * 0.125f;
    }
    __syncthreads();

    float4 acc = make_float4(0.f, 0.f, 0.f, 0.f);
    const float4* wk = (const float4*)(W + (size_t)(D_ + h * HD_) * D_) + t;
#pragma unroll 8
    for (int j = 0; j < HD_; j++) {
        float qv = qh[j];
        float4 w4 = wk[(size_t)j * (D_ / 4)];
        acc.x += qv * w4.x;
        acc.y += qv * w4.y;
        acc.z += qv * w4.z;
        acc.w += qv * w4.w;
    }
    ((float4*)(g_qproj + ((size_t)b * H_ + h) * D_))[t] = acc;
}

// ============================================================
// K2: flash chunk pass, FFMA2 packed math (R8-proven structure; FROZEN
// except epilogue store format -> fp16).
// grid = (NC_, B_), block = 256, 2 CTAs/SM.
// smem: qp[4096] | data[16384] | sc_raw[256] | sc2[512]
// ============================================================
__global__ __launch_bounds__(256, 2) void k2(const float* __restrict__ src) {
    extern __shared__ float smem[];
    float* qp = smem;                     // H_*D_
    float* data = qp + H_ * D_;           // CR_*D_
    float* sc_raw = data + CR_ * D_;      // CR_*8
    float* sc2 = sc_raw + CR_ * 8;        // CR_*16 (duplicated pairs)

    int c = blockIdx.x, b = blockIdx.y;
    int t = threadIdx.x, w = t >> 5, lane = t & 31;

    for (int i = t; i < H_ * D_ / 4; i += 256)
        ((float4*)qp)[i] = ((const float4*)(g_qproj + (size_t)b * H_ * D_))[i];
    __syncthreads();

    const float* srcb = src + ((size_t)c * CR_ * B_ + b) * D_;

    // ---------- Phase A: scores (packed f32x2) + stage rows ----------
    {
        int r0 = w * 4;
        unsigned long long p2[4][8];
#pragma unroll
        for (int rr = 0; rr < 4; rr++)
#pragma unroll
            for (int h = 0; h < 8; h++) p2[rr][h] = 0ull;

#pragma unroll
        for (int i = 0; i < 4; i++) {
            int fi = lane + 32 * i;
            FU s[4];
#pragma unroll
            for (int rr = 0; rr < 4; rr++) {
                s[rr].f4 = ((const float4*)(srcb + (size_t)(r0 + rr) * B_ * D_))[fi];
                ((float4*)(data + (size_t)(r0 + rr) * D_))[fi] = s[rr].f4;
            }
#pragma unroll
            for (int h = 0; h < 8; h++) {
                FU q;
                q.f4 = ((const float4*)(qp + h * D_))[fi];
#pragma unroll
                for (int rr = 0; rr < 4; rr++) {
                    fma2(p2[rr][h], s[rr].u2.x, q.u2.x);
                    fma2(p2[rr][h], s[rr].u2.y, q.u2.y);
                }
            }
        }
#pragma unroll
        for (int rr = 0; rr < 4; rr++)
#pragma unroll
            for (int h = 0; h < 8; h++) {
                FU1 pv; pv.u = p2[rr][h];
                float v = wsum(pv.f2.x + pv.f2.y);
                if (lane == 0) sc_raw[(r0 + rr) * 8 + h] = v;
            }
    }
    __syncthreads();

    // ---------- softmax: warp w = head w; write duplicated pairs ----------
    {
        int h = w;
        float v = sc_raw[lane * 8 + h];
        float m = wmax(v);
        float e = __expf(v - m);
        float l = wsum(e);
        sc2[lane * 16 + 2 * h] = e;
        sc2[lane * 16 + 2 * h + 1] = e;
        if (lane == 0) {
            g_m[(b * NC_ + c) * H_ + h] = m;
            g_l[(b * NC_ + c) * H_ + h] = l;
        }
    }
    __syncthreads();

    // ---------- Phase B: packed weighted accumulation, s split in halves ----------
    int half = t >> 7, f = t & 127;
    unsigned long long a2[8][2];
#pragma unroll
    for (int h = 0; h < 8; h++) { a2[h][0] = 0ull; a2[h][1] = 0ull; }

    int sbase = half * (CR_ / 2);
#pragma unroll 2
    for (int si = 0; si < CR_ / 2; si++) {
        int s = sbase + si;
        FU v;
        v.f4 = ((const float4*)data)[s * (D_ / 4) + f];
#pragma unroll
        for (int q = 0; q < 4; q++) {
            FU e;
            e.f4 = *(const float4*)(sc2 + s * 16 + q * 4);
            fma2(a2[2 * q][0], v.u2.x, e.u2.x);
            fma2(a2[2 * q][1], v.u2.y, e.u2.x);
            fma2(a2[2 * q + 1][0], v.u2.x, e.u2.y);
            fma2(a2[2 * q + 1][1], v.u2.y, e.u2.y);
        }
    }
    __syncthreads();

    // half 1 stores partials into reused data smem (padded stride 36 floats)
    if (half) {
#pragma unroll
        for (int h = 0; h < 8; h++) {
            FU o;
            o.u2.x = a2[h][0];
            o.u2.y = a2[h][1];
            ((float4*)(data + f * 36))[h] = o.f4;
        }
    }
    __syncthreads();
    if (!half) {
        __half* ab = g_accb + ((size_t)(b * NC_ + c) * H_) * D_;
#pragma unroll
        for (int h = 0; h < 8; h++) {
            FU m_;
            m_.u2.x = a2[h][0];
            m_.u2.y = a2[h][1];
            float4 o = ((const float4*)(data + f * 36))[h];
            o.x += m_.f4.x; o.y += m_.f4.y; o.z += m_.f4.z; o.w += m_.f4.w;
            HU hv;
            hv.h2[0] = __floats2half2_rn(o.x, o.y);
            hv.h2[1] = __floats2half2_rn(o.z, o.w);
            *(uint2*)(ab + h * D_ + 4 * f) = hv.u2;
        }
    }
}

// ============================================================
// K3ab: per (b,h): combine NC_ fp16 chunk partials with LSE weights,
// then project via Wv. grid = (H_, B_), block = 256
// ============================================================
__global__ __launch_bounds__(256) void k3ab(const float* __restrict__ W,
                                            const float* __restrict__ bias) {
    int h = blockIdx.x, b = blockIdx.y;
    int t = threadIdx.x, w = t >> 5, lane = t & 31;
    __shared__ float wgt[NC_];
    __shared__ float4 cs4[D_ / 4];
    __shared__ float4 part[D_ / 4];

    if (t < 32) {
        float m0 = g_m[(b * NC_ + lane) * H_ + h];
        float m1 = g_m[(b * NC_ + lane + 32) * H_ + h];
        float l0 = g_l[(b * NC_ + lane) * H_ + h];
        float l1 = g_l[(b * NC_ + lane + 32) * H_ + h];
        float m = wmax(fmaxf(m0, m1));
        float w0 = __expf(m0 - m);
        float w1 = __expf(m1 - m);
        float L = wsum(w0 * l0 + w1 * l1);
        wgt[lane] = w0 / L;
        wgt[lane + 32] = w1 / L;
    }
    __syncthreads();

    int half = t >> 7, f = t & 127;
    float4 acc = make_float4(0.f, 0.f, 0.f, 0.f);
    const __half* base = g_accb + ((size_t)b * NC_ * H_ + h) * D_ + 4 * f;
#pragma unroll 8
    for (int cc = half * 32; cc < half * 32 + 32; cc++) {
        HU hv;
        hv.u2 = __ldcs((const uint2*)(base + (size_t)cc * H_ * D_));
        float2 va = __half22float2(hv.h2[0]);
        float2 vb = __half22float2(hv.h2[1]);
        float wv = wgt[cc];
        acc.x += wv * va.x;
        acc.y += wv * va.y;
        acc.z += wv * vb.x;
        acc.w += wv * vb.y;
    }
    if (half) part[f] = acc;
    __syncthreads();
    if (!half) {
        float4 p = part[f];
        acc.x += p.x; acc.y += p.y; acc.z += p.z; acc.w += p.w;
        cs4[f] = acc;
    }
    __syncthreads();

    // Wv projection: 2 outputs in flight per warp iteration
#pragma unroll
    for (int ii = 0; ii < 4; ii++) {
        int ol0 = ii * 16 + w;
        int ol1 = ol0 + 8;
        const float4* wr0 = (const float4*)(W + (size_t)(2 * D_ + h * HD_ + ol0) * D_);
        const float4* wr1 = (const float4*)(W + (size_t)(2 * D_ + h * HD_ + ol1) * D_);
        float a0 = 0.f, a1 = 0.f;
#pragma unroll
        for (int kk = 0; kk < 4; kk++) {
            float4 x4 = cs4[lane + 32 * kk];
            float4 w40 = wr0[lane + 32 * kk];
            float4 w41 = wr1[lane + 32 * kk];
            a0 += w40.x * x4.x + w40.y * x4.y + w40.z * x4.z + w40.w * x4.w;
            a1 += w41.x * x4.x + w41.y * x4.y + w41.z * x4.z + w41.w * x4.w;
        }
        a0 = wsum(a0);
        a1 = wsum(a1);
        if (lane == 0) {
            g_ctx[b * D_ + h * HD_ + ol0] = a0 + bias[2 * D_ + h * HD_ + ol0];
            g_ctx[b * D_ + h * HD_ + ol1] = a1 + bias[2 * D_ + h * HD_ + ol1];
        }
    }
}

// ============================================================
// K3c: attn_out[b, i] = g_ctx[b,:] . Wo[i,:] + bo[i]
// grid = (8, B_), block = 256 — 2 outputs in flight per warp iteration
// ============================================================
__global__ __launch_bounds__(256) void k3c(const float* __restrict__ Wo,
                                           const float* __restrict__ bo) {
    int gx = blockIdx.x, b = blockIdx.y;
    int t = threadIdx.x, w = t >> 5, lane = t & 31;
    __shared__ float4 cx4[D_ / 4];
    if (t < 128) cx4[t] = ((const float4*)(g_ctx + (size_t)b * D_))[t];
    __syncthreads();

#pragma unroll
    for (int ii = 0; ii < 4; ii++) {
        int i0 = gx * 64 + ii * 16 + w;
        int i1 = i0 + 8;
        const float4* wr0 = (const float4*)(Wo + (size_t)i0 * D_);
        const float4* wr1 = (const float4*)(Wo + (size_t)i1 * D_);
        float a0 = 0.f, a1 = 0.f;
#pragma unroll
        for (int kk = 0; kk < 4; kk++) {
            float4 x4 = cx4[lane + 32 * kk];
            float4 w40 = wr0[lane + 32 * kk];
            float4 w41 = wr1[lane + 32 * kk];
            a0 += w40.x * x4.x + w40.y * x4.y + w40.z * x4.z + w40.w * x4.w;
            a1 += w41.x * x4.x + w41.y * x4.y + w41.z * x4.z + w41.w * x4.w;
        }
        a0 = wsum(a0);
        a1 = wsum(a1);
        if (lane == 0) {
            g_attn[b * D_ + i0] = a0 + bo[i0];
            g_attn[b * D_ + i1] = a1 + bo[i1];
        }
    }
}

// ============================================================
// K4: out[s,b,:] = LN(src[s,b,:] + attn_out[b,:])
// warp per row; grid = S_*B_/8, block = 256 (FROZEN — at DRAM roofline)
// ============================================================
__global__ __launch_bounds__(256) void k4(const float* __restrict__ src,
                                          const float* __restrict__ lnw,
                                          const float* __restrict__ lnb,
                                          float* __restrict__ out) {
    int r = blockIdx.x * 8 + (threadIdx.x >> 5);
    int lane = threadIdx.x & 31;
    int b = r & (B_ - 1);
    const float4* xs = (const float4*)(src + (size_t)r * D_);
    const float4* ao = (const float4*)(g_attn + b * D_);
    float4 x[4];
    float sum = 0.f, sq = 0.f;
#pragma unroll
    for (int i = 0; i < 4; i++) {
        int fi = lane + 32 * i;
        float4 a = __ldcs(xs + fi);
        float4 c = ao[fi];
        a.x += c.x; a.y += c.y; a.z += c.z; a.w += c.w;
        x[i] = a;
        sum += a.x + a.y + a.z + a.w;
        sq += a.x * a.x + a.y * a.y + a.z * a.z + a.w * a.w;
    }
    sum = wsum(sum);
    sq = wsum(sq);
    float mean = sum * (1.f / D_);
    float var = sq * (1.f / D_) - mean * mean;
    float rstd = rsqrtf(var + LNEPS);
    float4* op = (float4*)(out + (size_t)r * D_);
    const float4* w4p = (const float4*)lnw;
    const float4* b4p = (const float4*)lnb;
#pragma unroll
    for (int i = 0; i < 4; i++) {
        int fi = lane + 32 * i;
        float4 wv = w4p[fi];
        float4 bv = b4p[fi];
        float4 a = x[i];
        a.x = (a.x - mean) * rstd * wv.x + bv.x;
        a.y = (a.y - mean) * rstd * wv.y + bv.y;
        a.z = (a.z - mean) * rstd * wv.z + bv.z;
        a.w = (a.w - mean) * rstd * wv.w + bv.w;
        __stcs(op + fi, a);
    }
}

extern "C" void kernel_launch(void* const* d_in, const int* in_sizes, int n_in,
                              void* d_out, int out_size) {
    (void)in_sizes; (void)n_in; (void)out_size;
    const float* src  = (const float*)d_in[0];
    const int*   lens = (const int*)d_in[1];
    const float* W    = (const float*)d_in[2];
    const float* bias = (const float*)d_in[3];
    const float* Wo   = (const float*)d_in[4];
    const float* bo   = (const float*)d_in[5];
    const float* lnw  = (const float*)d_in[6];
    const float* lnb  = (const float*)d_in[7];
    float* out = (float*)d_out;

    const int k2_smem = (H_ * D_ + CR_ * D_ + CR_ * 8 + CR_ * 16) * sizeof(float);
    static bool attr_set = false;
    if (!attr_set) {
        cudaFuncSetAttribute(k2, cudaFuncAttributeMaxDynamicSharedMemorySize, k2_smem);
        attr_set = true;
    }

    k1<<<dim3(H_, B_), 128>>>(src, lens, W, bias);
    k2<<<dim3(NC_, B_), 256, k2_smem>>>(src);
    k3ab<<<dim3(H_, B_), 256>>>(W, bias);
    k3c<<<dim3(8, B_), 256>>>(Wo, bo);
    k4<<<(S_ * B_) / 8, 256>>>(src, lnw, lnb, out);
}

// round 16
// speedup vs baseline: 1.4472x; 1.0450x over previous
#include <cuda_runtime.h>
#include <cuda_fp16.h>

#define S_ 2048
#define B_ 64
#define D_ 512
#define H_ 8
#define HD_ 64
#define NC_ 64
#define CR_ 32            // rows per chunk = S_/NC_
#define LNEPS 1e-5f

// ---- scratch (static device globals; no runtime allocation) ----
__device__ float g_qproj[B_ * H_ * D_];               // 1 MB
__device__ __half g_accb[(size_t)B_ * NC_ * H_ * D_]; // 33.5 MB (fp16 partials)
__device__ float g_m[B_ * NC_ * H_];
__device__ float g_l[B_ * NC_ * H_];
__device__ float g_ctx[B_ * D_];
__device__ float g_attn[B_ * D_];

union FU { float4 f4; ulonglong2 u2; };
union FU1 { unsigned long long u; float2 f2; };
union HU { uint2 u2; __half2 h2[2]; };

__device__ __forceinline__ void fma2(unsigned long long& d,
                                     unsigned long long a,
                                     unsigned long long b) {
    asm("fma.rn.f32x2 %0, %1, %2, %0;" : "+l"(d) : "l"(a), "l"(b));
}

__device__ __forceinline__ float wsum(float v) {
#pragma unroll
    for (int o = 16; o; o >>= 1) v += __shfl_xor_sync(0xffffffffu, v, o);
    return v;
}
__device__ __forceinline__ float wmax(float v) {
#pragma unroll
    for (int o = 16; o; o >>= 1) v = fmaxf(v, __shfl_xor_sync(0xffffffffu, v, o));
    return v;
}

// ============================================================
// K1: block (h, b): q_h = (qin @ Wq_h^T + bq_h)*scale  (64 vals)
//     qproj[b,h,:] = sum_j q_h[j] * Wk[D_+h*64+j, :]
// grid = (H_, B_), block = 128
// ============================================================
__global__ __launch_bounds__(128) void k1(const float* __restrict__ src,
                                          const int* __restrict__ lens,
                                          const float* __restrict__ W,
                                          const float* __restrict__ bias) {
    int h = blockIdx.x, b = blockIdx.y;
    int t = threadIdx.x, w = t >> 5, lane = t & 31;
    __shared__ float4 qin4[D_ / 4];
    __shared__ float qh[HD_];

    int s0 = lens[b] - 1;
    qin4[t] = ((const float4*)(src + ((size_t)s0 * B_ + b) * D_))[t];
    __syncthreads();

#pragma unroll
    for (int i = 0; i < 16; i++) {
        int j = w * 16 + i;
        const float4* wr = (const float4*)(W + (size_t)(h * HD_ + j) * D_);
        float a = 0.f;
#pragma unroll
        for (int kk = 0; kk < 4; kk++) {
            float4 w4 = wr[lane + 32 * kk];
            float4 x4 = qin4[lane + 32 * kk];
            a += w4.x * x4.x + w4.y * x4.y + w4.z * x4.z + w4.w * x4.w;
        }
        a = wsum(a);
        if (lane == 0) qh[j] = (a + bias[h * HD_ + j]) * 0.125f;
    }
    __syncthreads();

    float4 acc = make_float4(0.f, 0.f, 0.f, 0.f);
    const float4* wk = (const float4*)(W + (size_t)(D_ + h * HD_) * D_) + t;
#pragma unroll 8
    for (int j = 0; j < HD_; j++) {
        float qv = qh[j];
        float4 w4 = wk[(size_t)j * (D_ / 4)];
        acc.x += qv * w4.x;
        acc.y += qv * w4.y;
        acc.z += qv * w4.z;
        acc.w += qv * w4.w;
    }
    ((float4*)(g_qproj + ((size_t)b * H_ + h) * D_))[t] = acc;
}

// ============================================================
// K2: flash chunk pass, FFMA2 packed math (R8 structure; phase A
// reduction replaced with 32-way butterfly multi-reduce).
// grid = (NC_, B_), block = 256, 2 CTAs/SM.
// smem: qp[4096] | data[16384] | sc_raw[256] | sc2[512]
// ============================================================
__global__ __launch_bounds__(256, 2) void k2(const float* __restrict__ src) {
    extern __shared__ float smem[];
    float* qp = smem;                     // H_*D_
    float* data = qp + H_ * D_;           // CR_*D_
    float* sc_raw = data + CR_ * D_;      // CR_*8
    float* sc2 = sc_raw + CR_ * 8;        // CR_*16 (duplicated pairs)

    int c = blockIdx.x, b = blockIdx.y;
    int t = threadIdx.x, w = t >> 5, lane = t & 31;

    for (int i = t; i < H_ * D_ / 4; i += 256)
        ((float4*)qp)[i] = ((const float4*)(g_qproj + (size_t)b * H_ * D_))[i];
    __syncthreads();

    const float* srcb = src + ((size_t)c * CR_ * B_ + b) * D_;

    // ---------- Phase A: scores (packed f32x2) + stage rows ----------
    {
        int r0 = w * 4;
        unsigned long long p2[4][8];
#pragma unroll
        for (int rr = 0; rr < 4; rr++)
#pragma unroll
            for (int h = 0; h < 8; h++) p2[rr][h] = 0ull;

#pragma unroll
        for (int i = 0; i < 4; i++) {
            int fi = lane + 32 * i;
            FU s[4];
#pragma unroll
            for (int rr = 0; rr < 4; rr++) {
                s[rr].f4 = ((const float4*)(srcb + (size_t)(r0 + rr) * B_ * D_))[fi];
                ((float4*)(data + (size_t)(r0 + rr) * D_))[fi] = s[rr].f4;
            }
#pragma unroll
            for (int h = 0; h < 8; h++) {
                FU q;
                q.f4 = ((const float4*)(qp + h * D_))[fi];
#pragma unroll
                for (int rr = 0; rr < 4; rr++) {
                    fma2(p2[rr][h], s[rr].u2.x, q.u2.x);
                    fma2(p2[rr][h], s[rr].u2.y, q.u2.y);
                }
            }
        }

        // butterfly multi-reduce: 32 targets (rr*8+h) across 32 lanes.
        // After 5 rounds, lane l holds the full sum for target l.
        float v[32];
#pragma unroll
        for (int rr = 0; rr < 4; rr++)
#pragma unroll
            for (int h = 0; h < 8; h++) {
                FU1 pv; pv.u = p2[rr][h];
                v[rr * 8 + h] = pv.f2.x + pv.f2.y;
            }
#pragma unroll
        for (int k = 16; k >= 1; k >>= 1) {
#pragma unroll
            for (int i = 0; i < k; i++) {
                float keep = (lane & k) ? v[i + k] : v[i];
                float send = (lane & k) ? v[i] : v[i + k];
                v[i] = keep + __shfl_xor_sync(0xffffffffu, send, k);
            }
        }
        sc_raw[(r0 + (lane >> 3)) * 8 + (lane & 7)] = v[0];
    }
    __syncthreads();

    // ---------- softmax: warp w = head w; write duplicated pairs ----------
    {
        int h = w;
        float v = sc_raw[lane * 8 + h];
        float m = wmax(v);
        float e = __expf(v - m);
        float l = wsum(e);
        sc2[lane * 16 + 2 * h] = e;
        sc2[lane * 16 + 2 * h + 1] = e;
        if (lane == 0) {
            g_m[(b * NC_ + c) * H_ + h] = m;
            g_l[(b * NC_ + c) * H_ + h] = l;
        }
    }
    __syncthreads();

    // ---------- Phase B: packed weighted accumulation, s split in halves ----------
    int half = t >> 7, f = t & 127;
    unsigned long long a2[8][2];
#pragma unroll
    for (int h = 0; h < 8; h++) { a2[h][0] = 0ull; a2[h][1] = 0ull; }

    int sbase = half * (CR_ / 2);
#pragma unroll 2
    for (int si = 0; si < CR_ / 2; si++) {
        int s = sbase + si;
        FU v;
        v.f4 = ((const float4*)data)[s * (D_ / 4) + f];
#pragma unroll
        for (int q = 0; q < 4; q++) {
            FU e;
            e.f4 = *(const float4*)(sc2 + s * 16 + q * 4);
            fma2(a2[2 * q][0], v.u2.x, e.u2.x);
            fma2(a2[2 * q][1], v.u2.y, e.u2.x);
            fma2(a2[2 * q + 1][0], v.u2.x, e.u2.y);
            fma2(a2[2 * q + 1][1], v.u2.y, e.u2.y);
        }
    }
    __syncthreads();

    // half 1 stores partials into reused data smem (padded stride 36 floats)
    if (half) {
#pragma unroll
        for (int h = 0; h < 8; h++) {
            FU o;
            o.u2.x = a2[h][0];
            o.u2.y = a2[h][1];
            ((float4*)(data + f * 36))[h] = o.f4;
        }
    }
    __syncthreads();
    if (!half) {
        __half* ab = g_accb + ((size_t)(b * NC_ + c) * H_) * D_;
#pragma unroll
        for (int h = 0; h < 8; h++) {
            FU m_;
            m_.u2.x = a2[h][0];
            m_.u2.y = a2[h][1];
            float4 o = ((const float4*)(data + f * 36))[h];
            o.x += m_.f4.x; o.y += m_.f4.y; o.z += m_.f4.z; o.w += m_.f4.w;
            HU hv;
            hv.h2[0] = __floats2half2_rn(o.x, o.y);
            hv.h2[1] = __floats2half2_rn(o.z, o.w);
            *(uint2*)(ab + h * D_ + 4 * f) = hv.u2;
        }
    }
}

// ============================================================
// K3ab: per (b,h): combine NC_ fp16 chunk partials with LSE weights,
// then project via Wv. grid = (H_, B_), block = 256
// ============================================================
__global__ __launch_bounds__(256) void k3ab(const float* __restrict__ W,
                                            const float* __restrict__ bias) {
    int h = blockIdx.x, b = blockIdx.y;
    int t = threadIdx.x, w = t >> 5, lane = t & 31;
    __shared__ float wgt[NC_];
    __shared__ float4 cs4[D_ / 4];
    __shared__ float4 part[D_ / 4];

    if (t < 32) {
        float m0 = g_m[(b * NC_ + lane) * H_ + h];
        float m1 = g_m[(b * NC_ + lane + 32) * H_ + h];
        float l0 = g_l[(b * NC_ + lane) * H_ + h];
        float l1 = g_l[(b * NC_ + lane + 32) * H_ + h];
        float m = wmax(fmaxf(m0, m1));
        float w0 = __expf(m0 - m);
        float w1 = __expf(m1 - m);
        float L = wsum(w0 * l0 + w1 * l1);
        wgt[lane] = w0 / L;
        wgt[lane + 32] = w1 / L;
    }
    __syncthreads();

    int half = t >> 7, f = t & 127;
    float4 acc = make_float4(0.f, 0.f, 0.f, 0.f);
    const __half* base = g_accb + ((size_t)b * NC_ * H_ + h) * D_ + 4 * f;
#pragma unroll 8
    for (int cc = half * 32; cc < half * 32 + 32; cc++) {
        HU hv;
        hv.u2 = __ldcs((const uint2*)(base + (size_t)cc * H_ * D_));
        float2 va = __half22float2(hv.h2[0]);
        float2 vb = __half22float2(hv.h2[1]);
        float wv = wgt[cc];
        acc.x += wv * va.x;
        acc.y += wv * va.y;
        acc.z += wv * vb.x;
        acc.w += wv * vb.y;
    }
    if (half) part[f] = acc;
    __syncthreads();
    if (!half) {
        float4 p = part[f];
        acc.x += p.x; acc.y += p.y; acc.z += p.z; acc.w += p.w;
        cs4[f] = acc;
    }
    __syncthreads();

    // Wv projection: 2 outputs in flight per warp iteration
#pragma unroll
    for (int ii = 0; ii < 4; ii++) {
        int ol0 = ii * 16 + w;
        int ol1 = ol0 + 8;
        const float4* wr0 = (const float4*)(W + (size_t)(2 * D_ + h * HD_ + ol0) * D_);
        const float4* wr1 = (const float4*)(W + (size_t)(2 * D_ + h * HD_ + ol1) * D_);
        float a0 = 0.f, a1 = 0.f;
#pragma unroll
        for (int kk = 0; kk < 4; kk++) {
            float4 x4 = cs4[lane + 32 * kk];
            float4 w40 = wr0[lane + 32 * kk];
            float4 w41 = wr1[lane + 32 * kk];
            a0 += w40.x * x4.x + w40.y * x4.y + w40.z * x4.z + w40.w * x4.w;
            a1 += w41.x * x4.x + w41.y * x4.y + w41.z * x4.z + w41.w * x4.w;
        }
        a0 = wsum(a0);
        a1 = wsum(a1);
        if (lane == 0) {
            g_ctx[b * D_ + h * HD_ + ol0] = a0 + bias[2 * D_ + h * HD_ + ol0];
            g_ctx[b * D_ + h * HD_ + ol1] = a1 + bias[2 * D_ + h * HD_ + ol1];
        }
    }
}

// ============================================================
// K3c: attn_out[b, i] = g_ctx[b,:] . Wo[i,:] + bo[i]
// grid = (8, B_), block = 256 — 2 outputs in flight per warp iteration
// ============================================================
__global__ __launch_bounds__(256) void k3c(const float* __restrict__ Wo,
                                           const float* __restrict__ bo) {
    int gx = blockIdx.x, b = blockIdx.y;
    int t = threadIdx.x, w = t >> 5, lane = t & 31;
    __shared__ float4 cx4[D_ / 4];
    if (t < 128) cx4[t] = ((const float4*)(g_ctx + (size_t)b * D_))[t];
    __syncthreads();

#pragma unroll
    for (int ii = 0; ii < 4; ii++) {
        int i0 = gx * 64 + ii * 16 + w;
        int i1 = i0 + 8;
        const float4* wr0 = (const float4*)(Wo + (size_t)i0 * D_);
        const float4* wr1 = (const float4*)(Wo + (size_t)i1 * D_);
        float a0 = 0.f, a1 = 0.f;
#pragma unroll
        for (int kk = 0; kk < 4; kk++) {
            float4 x4 = cx4[lane + 32 * kk];
            float4 w40 = wr0[lane + 32 * kk];
            float4 w41 = wr1[lane + 32 * kk];
            a0 += w40.x * x4.x + w40.y * x4.y + w40.z * x4.z + w40.w * x4.w;
            a1 += w41.x * x4.x + w41.y * x4.y + w41.z * x4.z + w41.w * x4.w;
        }
        a0 = wsum(a0);
        a1 = wsum(a1);
        if (lane == 0) {
            g_attn[b * D_ + i0] = a0 + bo[i0];
            g_attn[b * D_ + i1] = a1 + bo[i1];
        }
    }
}

// ============================================================
// K4: out[s,b,:] = LN(src[s,b,:] + attn_out[b,:])
// warp per row; grid = S_*B_/8, block = 256 (FROZEN — at DRAM roofline)
// ============================================================
__global__ __launch_bounds__(256) void k4(const float* __restrict__ src,
                                          const float* __restrict__ lnw,
                                          const float* __restrict__ lnb,
                                          float* __restrict__ out) {
    int r = blockIdx.x * 8 + (threadIdx.x >> 5);
    int lane = threadIdx.x & 31;
    int b = r & (B_ - 1);
    const float4* xs = (const float4*)(src + (size_t)r * D_);
    const float4* ao = (const float4*)(g_attn + b * D_);
    float4 x[4];
    float sum = 0.f, sq = 0.f;
#pragma unroll
    for (int i = 0; i < 4; i++) {
        int fi = lane + 32 * i;
        float4 a = __ldcs(xs + fi);
        float4 c = ao[fi];
        a.x += c.x; a.y += c.y; a.z += c.z; a.w += c.w;
        x[i] = a;
        sum += a.x + a.y + a.z + a.w;
        sq += a.x * a.x + a.y * a.y + a.z * a.z + a.w * a.w;
    }
    sum = wsum(sum);
    sq = wsum(sq);
    float mean = sum * (1.f / D_);
    float var = sq * (1.f / D_) - mean * mean;
    float rstd = rsqrtf(var + LNEPS);
    float4* op = (float4*)(out + (size_t)r * D_);
    const float4* w4p = (const float4*)lnw;
    const float4* b4p = (const float4*)lnb;
#pragma unroll
    for (int i = 0; i < 4; i++) {
        int fi = lane + 32 * i;
        float4 wv = w4p[fi];
        float4 bv = b4p[fi];
        float4 a = x[i];
        a.x = (a.x - mean) * rstd * wv.x + bv.x;
        a.y = (a.y - mean) * rstd * wv.y + bv.y;
        a.z = (a.z - mean) * rstd * wv.z + bv.z;
        a.w = (a.w - mean) * rstd * wv.w + bv.w;
        __stcs(op + fi, a);
    }
}

extern "C" void kernel_launch(void* const* d_in, const int* in_sizes, int n_in,
                              void* d_out, int out_size) {
    (void)in_sizes; (void)n_in; (void)out_size;
    const float* src  = (const float*)d_in[0];
    const int*   lens = (const int*)d_in[1];
    const float* W    = (const float*)d_in[2];
    const float* bias = (const float*)d_in[3];
    const float* Wo   = (const float*)d_in[4];
    const float* bo   = (const float*)d_in[5];
    const float* lnw  = (const float*)d_in[6];
    const float* lnb  = (const float*)d_in[7];
    float* out = (float*)d_out;

    const int k2_smem = (H_ * D_ + CR_ * D_ + CR_ * 8 + CR_ * 16) * sizeof(float);
    static bool attr_set = false;
    if (!attr_set) {
        cudaFuncSetAttribute(k2, cudaFuncAttributeMaxDynamicSharedMemorySize, k2_smem);
        attr_set = true;
    }

    k1<<<dim3(H_, B_), 128>>>(src, lens, W, bias);
    k2<<<dim3(NC_, B_), 256, k2_smem>>>(src);
    k3ab<<<dim3(H_, B_), 256>>>(W, bias);
    k3c<<<dim3(8, B_), 256>>>(Wo, bo);
    k4<<<(S_ * B_) / 8, 256>>>(src, lnw, lnb, out);
}

// round 17
// speedup vs baseline: 1.5740x; 1.0876x over previous
#include <cuda_runtime.h>
#include <cuda_fp16.h>

#define S_ 2048
#define B_ 64
#define D_ 512
#define H_ 8
#define HD_ 64
#define NC_ 64
#define CR_ 32            // rows per chunk = S_/NC_
#define LNEPS 1e-5f

// ---- scratch (static device globals; no runtime allocation) ----
__device__ float g_qproj[B_ * H_ * D_];               // 1 MB
__device__ __half g_accb[(size_t)B_ * NC_ * H_ * D_]; // 33.5 MB (fp16 partials)
__device__ float g_m[B_ * NC_ * H_];
__device__ float g_l[B_ * NC_ * H_];
__device__ float g_ctx[B_ * D_];
__device__ float g_attn[B_ * D_];

union FU { float4 f4; ulonglong2 u2; };
union FU1 { unsigned long long u; float2 f2; };
union HU { uint2 u2; __half2 h2[2]; };

__device__ __forceinline__ void fma2(unsigned long long& d,
                                     unsigned long long a,
                                     unsigned long long b) {
    asm("fma.rn.f32x2 %0, %1, %2, %0;" : "+l"(d) : "l"(a), "l"(b));
}

__device__ __forceinline__ float wsum(float v) {
#pragma unroll
    for (int o = 16; o; o >>= 1) v += __shfl_xor_sync(0xffffffffu, v, o);
    return v;
}
__device__ __forceinline__ float wmax(float v) {
#pragma unroll
    for (int o = 16; o; o >>= 1) v = fmaxf(v, __shfl_xor_sync(0xffffffffu, v, o));
    return v;
}

// ============================================================
// K1: block (h, b): q_h = (qin @ Wq_h^T + bq_h)*scale  (64 vals)
//     qproj[b,h,:] = sum_j q_h[j] * Wk[D_+h*64+j, :]
// grid = (H_, B_), block = 128
// ============================================================
__global__ __launch_bounds__(128) void k1(const float* __restrict__ src,
                                          const int* __restrict__ lens,
                                          const float* __restrict__ W,
                                          const float* __restrict__ bias) {
    int h = blockIdx.x, b = blockIdx.y;
    int t = threadIdx.x, w = t >> 5, lane = t & 31;
    __shared__ float4 qin4[D_ / 4];
    __shared__ float qh[HD_];

    int s0 = lens[b] - 1;
    qin4[t] = ((const float4*)(src + ((size_t)s0 * B_ + b) * D_))[t];
    __syncthreads();

#pragma unroll
    for (int i = 0; i < 16; i++) {
        int j = w * 16 + i;
        const float4* wr = (const float4*)(W + (size_t)(h * HD_ + j) * D_);
        float a = 0.f;
#pragma unroll
        for (int kk = 0; kk < 4; kk++) {
            float4 w4 = wr[lane + 32 * kk];
            float4 x4 = qin4[lane + 32 * kk];
            a += w4.x * x4.x + w4.y * x4.y + w4.z * x4.z + w4.w * x4.w;
        }
        a = wsum(a);
        if (lane == 0) qh[j] = (a + bias[h * HD_ + j]) * 0.125f;
    }
    __syncthreads();

    float4 acc = make_float4(0.f, 0.f, 0.f, 0.f);
    const float4* wk = (const float4*)(W + (size_t)(D_ + h * HD_) * D_) + t;
#pragma unroll 8
    for (int j = 0; j < HD_; j++) {
        float qv = qh[j];
        float4 w4 = wk[(size_t)j * (D_ / 4)];
        acc.x += qv * w4.x;
        acc.y += qv * w4.y;
        acc.z += qv * w4.z;
        acc.w += qv * w4.w;
    }
    ((float4*)(g_qproj + ((size_t)b * H_ + h) * D_))[t] = acc;
}

// ============================================================
// K2: flash chunk pass, FFMA2 packed math, butterfly multi-reduce.
// grid = (NC_, B_), block = 256, 2 CTAs/SM.
// smem: qp[4096] | data[16384] | sc_raw[256] | sc2[512]
// ============================================================
__global__ __launch_bounds__(256, 2) void k2(const float* __restrict__ src) {
    extern __shared__ float smem[];
    float* qp = smem;                     // H_*D_
    float* data = qp + H_ * D_;           // CR_*D_
    float* sc_raw = data + CR_ * D_;      // CR_*8
    float* sc2 = sc_raw + CR_ * 8;        // CR_*16 (duplicated pairs)

    int c = blockIdx.x, b = blockIdx.y;
    int t = threadIdx.x, w = t >> 5, lane = t & 31;

    for (int i = t; i < H_ * D_ / 4; i += 256)
        ((float4*)qp)[i] = ((const float4*)(g_qproj + (size_t)b * H_ * D_))[i];
    __syncthreads();

    const float* srcb = src + ((size_t)c * CR_ * B_ + b) * D_;

    // ---------- Phase A: scores (packed f32x2) + stage rows ----------
    {
        int r0 = w * 4;
        unsigned long long p2[4][8];
#pragma unroll
        for (int rr = 0; rr < 4; rr++)
#pragma unroll
            for (int h = 0; h < 8; h++) p2[rr][h] = 0ull;

#pragma unroll
        for (int i = 0; i < 4; i++) {
            int fi = lane + 32 * i;
            FU s[4];
#pragma unroll
            for (int rr = 0; rr < 4; rr++) {
                s[rr].f4 = __ldcs((const float4*)(srcb + (size_t)(r0 + rr) * B_ * D_) + fi);
                ((float4*)(data + (size_t)(r0 + rr) * D_))[fi] = s[rr].f4;
            }
#pragma unroll
            for (int h = 0; h < 8; h++) {
                FU q;
                q.f4 = ((const float4*)(qp + h * D_))[fi];
#pragma unroll
                for (int rr = 0; rr < 4; rr++) {
                    fma2(p2[rr][h], s[rr].u2.x, q.u2.x);
                    fma2(p2[rr][h], s[rr].u2.y, q.u2.y);
                }
            }
        }

        // butterfly multi-reduce: 32 targets (rr*8+h) across 32 lanes.
        float v[32];
#pragma unroll
        for (int rr = 0; rr < 4; rr++)
#pragma unroll
            for (int h = 0; h < 8; h++) {
                FU1 pv; pv.u = p2[rr][h];
                v[rr * 8 + h] = pv.f2.x + pv.f2.y;
            }
#pragma unroll
        for (int k = 16; k >= 1; k >>= 1) {
#pragma unroll
            for (int i = 0; i < k; i++) {
                float keep = (lane & k) ? v[i + k] : v[i];
                float send = (lane & k) ? v[i] : v[i + k];
                v[i] = keep + __shfl_xor_sync(0xffffffffu, send, k);
            }
        }
        sc_raw[(r0 + (lane >> 3)) * 8 + (lane & 7)] = v[0];
    }
    __syncthreads();

    // ---------- softmax: warp w = head w; write duplicated pairs ----------
    {
        int h = w;
        float v = sc_raw[lane * 8 + h];
        float m = wmax(v);
        float e = __expf(v - m);
        float l = wsum(e);
        sc2[lane * 16 + 2 * h] = e;
        sc2[lane * 16 + 2 * h + 1] = e;
        if (lane == 0) {
            g_m[(b * NC_ + c) * H_ + h] = m;
            g_l[(b * NC_ + c) * H_ + h] = l;
        }
    }
    __syncthreads();

    // ---------- Phase B: packed weighted accumulation, s split in halves ----------
    int half = t >> 7, f = t & 127;
    unsigned long long a2[8][2];
#pragma unroll
    for (int h = 0; h < 8; h++) { a2[h][0] = 0ull; a2[h][1] = 0ull; }

    int sbase = half * (CR_ / 2);
#pragma unroll 2
    for (int si = 0; si < CR_ / 2; si++) {
        int s = sbase + si;
        FU v;
        v.f4 = ((const float4*)data)[s * (D_ / 4) + f];
#pragma unroll
        for (int q = 0; q < 4; q++) {
            FU e;
            e.f4 = *(const float4*)(sc2 + s * 16 + q * 4);
            fma2(a2[2 * q][0], v.u2.x, e.u2.x);
            fma2(a2[2 * q][1], v.u2.y, e.u2.x);
            fma2(a2[2 * q + 1][0], v.u2.x, e.u2.y);
            fma2(a2[2 * q + 1][1], v.u2.y, e.u2.y);
        }
    }
    __syncthreads();

    // half 1 stores partials into reused data smem (padded stride 36 floats)
    if (half) {
#pragma unroll
        for (int h = 0; h < 8; h++) {
            FU o;
            o.u2.x = a2[h][0];
            o.u2.y = a2[h][1];
            ((float4*)(data + f * 36))[h] = o.f4;
        }
    }
    __syncthreads();
    if (!half) {
        __half* ab = g_accb + ((size_t)(b * NC_ + c) * H_) * D_;
#pragma unroll
        for (int h = 0; h < 8; h++) {
            FU m_;
            m_.u2.x = a2[h][0];
            m_.u2.y = a2[h][1];
            float4 o = ((const float4*)(data + f * 36))[h];
            o.x += m_.f4.x; o.y += m_.f4.y; o.z += m_.f4.z; o.w += m_.f4.w;
            HU hv;
            hv.h2[0] = __floats2half2_rn(o.x, o.y);
            hv.h2[1] = __floats2half2_rn(o.z, o.w);
            *(uint2*)(ab + h * D_ + 4 * f) = hv.u2;
        }
    }
}

// ============================================================
// K3ab: per (b,h): combine NC_ fp16 chunk partials with LSE weights,
// then project via Wv (4-way output ILP). grid = (H_, B_), block = 256
// ============================================================
__global__ __launch_bounds__(256) void k3ab(const float* __restrict__ W,
                                            const float* __restrict__ bias) {
    int h = blockIdx.x, b = blockIdx.y;
    int t = threadIdx.x, w = t >> 5, lane = t & 31;
    __shared__ float wgt[NC_];
    __shared__ float4 cs4[D_ / 4];
    __shared__ float4 part[D_ / 4];

    if (t < 32) {
        float m0 = g_m[(b * NC_ + lane) * H_ + h];
        float m1 = g_m[(b * NC_ + lane + 32) * H_ + h];
        float l0 = g_l[(b * NC_ + lane) * H_ + h];
        float l1 = g_l[(b * NC_ + lane + 32) * H_ + h];
        float m = wmax(fmaxf(m0, m1));
        float w0 = __expf(m0 - m);
        float w1 = __expf(m1 - m);
        float L = wsum(w0 * l0 + w1 * l1);
        wgt[lane] = w0 / L;
        wgt[lane + 32] = w1 / L;
    }
    __syncthreads();

    int half = t >> 7, f = t & 127;
    float4 acc = make_float4(0.f, 0.f, 0.f, 0.f);
    const __half* base = g_accb + ((size_t)b * NC_ * H_ + h) * D_ + 4 * f;
#pragma unroll 8
    for (int cc = half * 32; cc < half * 32 + 32; cc++) {
        HU hv;
        hv.u2 = __ldcs((const uint2*)(base + (size_t)cc * H_ * D_));
        float2 va = __half22float2(hv.h2[0]);
        float2 vb = __half22float2(hv.h2[1]);
        float wv = wgt[cc];
        acc.x += wv * va.x;
        acc.y += wv * va.y;
        acc.z += wv * vb.x;
        acc.w += wv * vb.y;
    }
    if (half) part[f] = acc;
    __syncthreads();
    if (!half) {
        float4 p = part[f];
        acc.x += p.x; acc.y += p.y; acc.z += p.z; acc.w += p.w;
        cs4[f] = acc;
    }
    __syncthreads();

    // Wv projection: 4 outputs in flight per warp iteration
#pragma unroll
    for (int ii = 0; ii < 2; ii++) {
        int ol0 = ii * 32 + w;
        const float4* wr0 = (const float4*)(W + (size_t)(2 * D_ + h * HD_ + ol0) * D_);
        const float4* wr1 = (const float4*)(W + (size_t)(2 * D_ + h * HD_ + ol0 + 8) * D_);
        const float4* wr2 = (const float4*)(W + (size_t)(2 * D_ + h * HD_ + ol0 + 16) * D_);
        const float4* wr3 = (const float4*)(W + (size_t)(2 * D_ + h * HD_ + ol0 + 24) * D_);
        float a0 = 0.f, a1 = 0.f, a2_ = 0.f, a3 = 0.f;
#pragma unroll
        for (int kk = 0; kk < 4; kk++) {
            float4 x4 = cs4[lane + 32 * kk];
            float4 w40 = wr0[lane + 32 * kk];
            float4 w41 = wr1[lane + 32 * kk];
            float4 w42 = wr2[lane + 32 * kk];
            float4 w43 = wr3[lane + 32 * kk];
            a0 += w40.x * x4.x + w40.y * x4.y + w40.z * x4.z + w40.w * x4.w;
            a1 += w41.x * x4.x + w41.y * x4.y + w41.z * x4.z + w41.w * x4.w;
            a2_ += w42.x * x4.x + w42.y * x4.y + w42.z * x4.z + w42.w * x4.w;
            a3 += w43.x * x4.x + w43.y * x4.y + w43.z * x4.z + w43.w * x4.w;
        }
        a0 = wsum(a0);
        a1 = wsum(a1);
        a2_ = wsum(a2_);
        a3 = wsum(a3);
        if (lane == 0) {
            int o = b * D_ + h * HD_ + ol0;
            int bb = 2 * D_ + h * HD_ + ol0;
            g_ctx[o] = a0 + bias[bb];
            g_ctx[o + 8] = a1 + bias[bb + 8];
            g_ctx[o + 16] = a2_ + bias[bb + 16];
            g_ctx[o + 24] = a3 + bias[bb + 24];
        }
    }
}

// ============================================================
// K3c: attn_out[b, i] = g_ctx[b,:] . Wo[i,:] + bo[i]
// grid = (8, B_), block = 256 — 4 outputs in flight per warp iteration
// ============================================================
__global__ __launch_bounds__(256) void k3c(const float* __restrict__ Wo,
                                           const float* __restrict__ bo) {
    int gx = blockIdx.x, b = blockIdx.y;
    int t = threadIdx.x, w = t >> 5, lane = t & 31;
    __shared__ float4 cx4[D_ / 4];
    if (t < 128) cx4[t] = ((const float4*)(g_ctx + (size_t)b * D_))[t];
    __syncthreads();

#pragma unroll
    for (int ii = 0; ii < 2; ii++) {
        int i0 = gx * 64 + ii * 32 + w;
        const float4* wr0 = (const float4*)(Wo + (size_t)i0 * D_);
        const float4* wr1 = (const float4*)(Wo + (size_t)(i0 + 8) * D_);
        const float4* wr2 = (const float4*)(Wo + (size_t)(i0 + 16) * D_);
        const float4* wr3 = (const float4*)(Wo + (size_t)(i0 + 24) * D_);
        float a0 = 0.f, a1 = 0.f, a2_ = 0.f, a3 = 0.f;
#pragma unroll
        for (int kk = 0; kk < 4; kk++) {
            float4 x4 = cx4[lane + 32 * kk];
            float4 w40 = wr0[lane + 32 * kk];
            float4 w41 = wr1[lane + 32 * kk];
            float4 w42 = wr2[lane + 32 * kk];
            float4 w43 = wr3[lane + 32 * kk];
            a0 += w40.x * x4.x + w40.y * x4.y + w40.z * x4.z + w40.w * x4.w;
            a1 += w41.x * x4.x + w41.y * x4.y + w41.z * x4.z + w41.w * x4.w;
            a2_ += w42.x * x4.x + w42.y * x4.y + w42.z * x4.z + w42.w * x4.w;
            a3 += w43.x * x4.x + w43.y * x4.y + w43.z * x4.z + w43.w * x4.w;
        }
        a0 = wsum(a0);
        a1 = wsum(a1);
        a2_ = wsum(a2_);
        a3 = wsum(a3);
        if (lane == 0) {
            g_attn[b * D_ + i0] = a0 + bo[i0];
            g_attn[b * D_ + i0 + 8] = a1 + bo[i0 + 8];
            g_attn[b * D_ + i0 + 16] = a2_ + bo[i0 + 16];
            g_attn[b * D_ + i0 + 24] = a3 + bo[i0 + 24];
        }
    }
}

// ============================================================
// K4: out[s,b,:] = LN(src[s,b,:] + attn_out[b,:])
// warp per row; grid = S_*B_/8, block = 256 (FROZEN — at DRAM roofline)
// ============================================================
__global__ __launch_bounds__(256) void k4(const float* __restrict__ src,
                                          const float* __restrict__ lnw,
                                          const float* __restrict__ lnb,
                                          float* __restrict__ out) {
    int r = blockIdx.x * 8 + (threadIdx.x >> 5);
    int lane = threadIdx.x & 31;
    int b = r & (B_ - 1);
    const float4* xs = (const float4*)(src + (size_t)r * D_);
    const float4* ao = (const float4*)(g_attn + b * D_);
    float4 x[4];
    float sum = 0.f, sq = 0.f;
#pragma unroll
    for (int i = 0; i < 4; i++) {
        int fi = lane + 32 * i;
        float4 a = __ldcs(xs + fi);
        float4 c = ao[fi];
        a.x += c.x; a.y += c.y; a.z += c.z; a.w += c.w;
        x[i] = a;
        sum += a.x + a.y + a.z + a.w;
        sq += a.x * a.x + a.y * a.y + a.z * a.z + a.w * a.w;
    }
    sum = wsum(sum);
    sq = wsum(sq);
    float mean = sum * (1.f / D_);
    float var = sq * (1.f / D_) - mean * mean;
    float rstd = rsqrtf(var + LNEPS);
    float4* op = (float4*)(out + (size_t)r * D_);
    const float4* w4p = (const float4*)lnw;
    const float4* b4p = (const float4*)lnb;
#pragma unroll
    for (int i = 0; i < 4; i++) {
        int fi = lane + 32 * i;
        float4 wv = w4p[fi];
        float4 bv = b4p[fi];
        float4 a = x[i];
        a.x = (a.x - mean) * rstd * wv.x + bv.x;
        a.y = (a.y - mean) * rstd * wv.y + bv.y;
        a.z = (a.z - mean) * rstd * wv.z + bv.z;
        a.w = (a.w - mean) * rstd * wv.w + bv.w;
        __stcs(op + fi, a);
    }
}

extern "C" void kernel_launch(void* const* d_in, const int* in_sizes, int n_in,
                              void* d_out, int out_size) {
    (void)in_sizes; (void)n_in; (void)out_size;
    const float* src  = (const float*)d_in[0];
    const int*   lens = (const int*)d_in[1];
    const float* W    = (const float*)d_in[2];
    const float* bias = (const float*)d_in[3];
    const float* Wo   = (const float*)d_in[4];
    const float* bo   = (const float*)d_in[5];
    const float* lnw  = (const float*)d_in[6];
    const float* lnb  = (const float*)d_in[7];
    float* out = (float*)d_out;

    const int k2_smem = (H_ * D_ + CR_ * D_ + CR_ * 8 + CR_ * 16) * sizeof(float);
    static bool attr_set = false;
    if (!attr_set) {
        cudaFuncSetAttribute(k2, cudaFuncAttributeMaxDynamicSharedMemorySize, k2_smem);
        attr_set = true;
    }

    k1<<<dim3(H_, B_), 128>>>(src, lens, W, bias);
    k2<<<dim3(NC_, B_), 256, k2_smem>>>(src);
    k3ab<<<dim3(H_, B_), 256>>>(W, bias);
    k3c<<<dim3(8, B_), 256>>>(Wo, bo);
    k4<<<(S_ * B_) / 8, 256>>>(src, lnw, lnb, out);
}